// round 1
// baseline (speedup 1.0000x reference)
#include <cuda_runtime.h>
#include <cuda_bf16.h>
#include <cstdint>

// Problem constants
#define B_    2
#define S_    2048
#define HID_  4096
#define NH_   32
#define NKV_  8
#define HD_   128
#define QSZ   (NH_ * HD_)          // 4096
#define KVSZ  (NKV_ * HD_)         // 1024
#define OSZ   (QSZ + 2 * KVSZ)     // 6144
#define TOK   (B_ * S_)            // 4096

__device__ float g_qkv[TOK * OSZ];   // QKV projection output (rope applied in place)
__device__ float g_attn[TOK * QSZ];  // attention output, [b,s, h*128+d]

// ============================================================================
// GEMM: C[M,N] = A[M,K] * Bw[N,K]^T   (both row-major, K contiguous)
// 128x128 tile, BK=16, 256 threads, 8x8 register micro-tile.
// ============================================================================
#define GBM 128
#define GBN 128
#define GBK 16

__global__ __launch_bounds__(256) void gemm_nt(const float* __restrict__ A,
                                               const float* __restrict__ Bw,
                                               float* __restrict__ C,
                                               int M, int N, int K) {
    __shared__ float As[GBK][GBM + 4];
    __shared__ float Bs[GBK][GBN + 4];

    const int t  = threadIdx.x;
    const int tx = t & 15;
    const int ty = t >> 4;

    const float* Ab = A  + (size_t)blockIdx.y * GBM * K;
    const float* Bb = Bw + (size_t)blockIdx.x * GBN * K;

    float acc[8][8];
#pragma unroll
    for (int i = 0; i < 8; i++)
#pragma unroll
        for (int j = 0; j < 8; j++) acc[i][j] = 0.0f;

    for (int k0 = 0; k0 < K; k0 += GBK) {
        // Load 128x16 tiles of A and B, storing transposed: As[k][m], Bs[k][n]
#pragma unroll
        for (int i = 0; i < 2; i++) {
            int idx = t + i * 256;          // 0..511
            int row = idx >> 2;             // 0..127
            int c4  = (idx & 3) * 4;        // 0,4,8,12
            float4 va = *(const float4*)(Ab + (size_t)row * K + k0 + c4);
            As[c4 + 0][row] = va.x; As[c4 + 1][row] = va.y;
            As[c4 + 2][row] = va.z; As[c4 + 3][row] = va.w;
            float4 vb = *(const float4*)(Bb + (size_t)row * K + k0 + c4);
            Bs[c4 + 0][row] = vb.x; Bs[c4 + 1][row] = vb.y;
            Bs[c4 + 2][row] = vb.z; Bs[c4 + 3][row] = vb.w;
        }
        __syncthreads();

#pragma unroll
        for (int kk = 0; kk < GBK; kk++) {
            float a[8], b[8];
            *(float4*)&a[0] = *(const float4*)&As[kk][ty * 8];
            *(float4*)&a[4] = *(const float4*)&As[kk][ty * 8 + 4];
            *(float4*)&b[0] = *(const float4*)&Bs[kk][tx * 8];
            *(float4*)&b[4] = *(const float4*)&Bs[kk][tx * 8 + 4];
#pragma unroll
            for (int i = 0; i < 8; i++)
#pragma unroll
                for (int j = 0; j < 8; j++)
                    acc[i][j] += a[i] * b[j];
        }
        __syncthreads();
    }

    float* Cb = C + (size_t)(blockIdx.y * GBM + ty * 8) * N + blockIdx.x * GBN + tx * 8;
#pragma unroll
    for (int i = 0; i < 8; i++) {
        *(float4*)(Cb + (size_t)i * N)     = make_float4(acc[i][0], acc[i][1], acc[i][2], acc[i][3]);
        *(float4*)(Cb + (size_t)i * N + 4) = make_float4(acc[i][4], acc[i][5], acc[i][6], acc[i][7]);
    }
}

// ============================================================================
// RoPE applied in place to Q (32 heads) and K (8 heads) of g_qkv.
// One thread per rotation pair (d, d+64).
// ============================================================================
__global__ __launch_bounds__(256) void rope_kernel(float* __restrict__ qkv,
                                                   const float* __restrict__ cosb,
                                                   const float* __restrict__ sinb) {
    int p = blockIdx.x * blockDim.x + threadIdx.x;
    // total pairs = TOK * (NH+NKV) * 64
    int d    = p & 63;
    int rest = p >> 6;
    int hh   = rest % (NH_ + NKV_);
    int bs   = rest / (NH_ + NKV_);
    if (bs >= TOK) return;

    size_t base = (size_t)bs * OSZ;
    int off = (hh < NH_) ? (hh * HD_) : (QSZ + (hh - NH_) * HD_);

    float x1 = qkv[base + off + d];
    float x2 = qkv[base + off + d + 64];
    size_t cb = (size_t)bs * HD_;
    float c1 = cosb[cb + d],      s1 = sinb[cb + d];
    float c2 = cosb[cb + d + 64], s2 = sinb[cb + d + 64];

    qkv[base + off + d]      = x1 * c1 - x2 * s1;
    qkv[base + off + d + 64] = x2 * c2 + x1 * s2;
}

// ============================================================================
// Flash attention, fp32. Tile 64(q) x 64(kv), HD=128. 256 threads.
// Qt, Kt stored transposed [HD][64+pad] for conflict-free fragment loads.
// V aliases Kt's smem region (natural layout [64][128]).
// ============================================================================
#define AQ 64
#define AK 64
#define QT_STRIDE 68         // 64 + 4 pad
#define SS_STRIDE 68
#define ATTN_SMEM_FLOATS (HD_ * QT_STRIDE + HD_ * QT_STRIDE + AQ * SS_STRIDE + 3 * AQ)
#define ATTN_SMEM_BYTES  (ATTN_SMEM_FLOATS * 4)

__global__ __launch_bounds__(256) void attn_kernel(const float* __restrict__ qkv,
                                                   float* __restrict__ out) {
    extern __shared__ float sm[];
    float* Qt   = sm;                          // [128][68]
    float* Kt   = Qt + HD_ * QT_STRIDE;        // [128][68]; aliased by Vs
    float* Vs   = Kt;                          // [64][128]  (8192 <= 8704 floats)
    float* Ss   = Kt + HD_ * QT_STRIDE;        // [64][68]
    float* rowm = Ss + AQ * SS_STRIDE;
    float* rowl = rowm + AQ;
    float* rowf = rowl + AQ;

    const int qt = (int)gridDim.x - 1 - (int)blockIdx.x;   // longest blocks first
    const int bh = blockIdx.y;
    const int b  = bh >> 5;           // / NH_
    const int h  = bh & 31;
    const int kvh = h >> 2;           // GQA group

    const float* qbase = qkv + (size_t)b * S_ * OSZ + h * HD_;
    const float* kbase = qkv + (size_t)b * S_ * OSZ + QSZ + kvh * HD_;
    const float* vbase = kbase + KVSZ;

    const int t  = threadIdx.x;
    const int tx = t & 15;
    const int ty = t >> 4;
    const int q0 = qt * AQ;

    const float scaling = 0.08838834764831843f;   // HD^-0.5

    // Load Q tile transposed: Qt[col][row]
#pragma unroll
    for (int i = 0; i < 8; i++) {
        int idx = t + i * 256;        // 0..2047 (64 rows x 32 float4)
        int r   = idx >> 5;
        int c4  = (idx & 31) * 4;
        float4 v = *(const float4*)(qbase + (size_t)(q0 + r) * OSZ + c4);
        Qt[(c4 + 0) * QT_STRIDE + r] = v.x;
        Qt[(c4 + 1) * QT_STRIDE + r] = v.y;
        Qt[(c4 + 2) * QT_STRIDE + r] = v.z;
        Qt[(c4 + 3) * QT_STRIDE + r] = v.w;
    }
    if (t < AQ) { rowm[t] = -1e30f; rowl[t] = 0.0f; }

    float o[4][8];
#pragma unroll
    for (int i = 0; i < 4; i++)
#pragma unroll
        for (int j = 0; j < 8; j++) o[i][j] = 0.0f;

    const int ntiles = qt + 1;
    for (int kt = 0; kt < ntiles; kt++) {
        const int k0 = kt * AK;
        __syncthreads();   // protects Vs/Ss from previous iteration; orders Q load

        // Load K tile transposed
#pragma unroll
        for (int i = 0; i < 8; i++) {
            int idx = t + i * 256;
            int r   = idx >> 5;
            int c4  = (idx & 31) * 4;
            float4 v = *(const float4*)(kbase + (size_t)(k0 + r) * OSZ + c4);
            Kt[(c4 + 0) * QT_STRIDE + r] = v.x;
            Kt[(c4 + 1) * QT_STRIDE + r] = v.y;
            Kt[(c4 + 2) * QT_STRIDE + r] = v.z;
            Kt[(c4 + 3) * QT_STRIDE + r] = v.w;
        }
        __syncthreads();

        // S = Q K^T  (64x64), 4x4 per thread at (ty*4+i, tx*4+j)
        float s[4][4];
#pragma unroll
        for (int i = 0; i < 4; i++)
#pragma unroll
            for (int j = 0; j < 4; j++) s[i][j] = 0.0f;

#pragma unroll 8
        for (int kk = 0; kk < HD_; kk++) {
            float a[4], bf[4];
            *(float4*)a  = *(const float4*)&Qt[kk * QT_STRIDE + ty * 4];
            *(float4*)bf = *(const float4*)&Kt[kk * QT_STRIDE + tx * 4];
#pragma unroll
            for (int i = 0; i < 4; i++)
#pragma unroll
                for (int j = 0; j < 4; j++)
                    s[i][j] += a[i] * bf[j];
        }

        // scale + causal mask, write to Ss
        const bool diag = (kt == qt);
#pragma unroll
        for (int i = 0; i < 4; i++) {
            int r = ty * 4 + i;
#pragma unroll
            for (int j = 0; j < 4; j++) {
                int c = tx * 4 + j;
                float v = s[i][j] * scaling;
                if (diag && (k0 + c > q0 + r)) v = -1e30f;
                Ss[r * SS_STRIDE + c] = v;
            }
        }
        __syncthreads();   // Kt reads done -> Vs load safe; Ss complete

        // Load V tile (natural layout), overwriting Kt region
#pragma unroll
        for (int i = 0; i < 8; i++) {
            int idx = t + i * 256;
            int r   = idx >> 5;
            int c4  = (idx & 31) * 4;
            *(float4*)&Vs[r * HD_ + c4] =
                *(const float4*)(vbase + (size_t)(k0 + r) * OSZ + c4);
        }

        // Online softmax: 4 threads per row, 16 cols each
        {
            int r   = t >> 2;
            int seg = (t & 3) * 16;
            float mOld = rowm[r];
            float mx = mOld;
#pragma unroll
            for (int j = 0; j < 16; j++)
                mx = fmaxf(mx, Ss[r * SS_STRIDE + seg + j]);
            mx = fmaxf(mx, __shfl_xor_sync(0xFFFFFFFFu, mx, 1));
            mx = fmaxf(mx, __shfl_xor_sync(0xFFFFFFFFu, mx, 2));
            float sum = 0.0f;
#pragma unroll
            for (int j = 0; j < 16; j++) {
                float p = __expf(Ss[r * SS_STRIDE + seg + j] - mx);
                Ss[r * SS_STRIDE + seg + j] = p;
                sum += p;
            }
            sum += __shfl_xor_sync(0xFFFFFFFFu, sum, 1);
            sum += __shfl_xor_sync(0xFFFFFFFFu, sum, 2);
            if ((t & 3) == 0) {
                float f = __expf(mOld - mx);
                rowl[r] = rowl[r] * f + sum;
                rowm[r] = mx;
                rowf[r] = f;
            }
        }
        __syncthreads();

        // Rescale accumulators, then O += P * V
#pragma unroll
        for (int i = 0; i < 4; i++) {
            float f = rowf[ty * 4 + i];
#pragma unroll
            for (int j = 0; j < 8; j++) o[i][j] *= f;
        }

#pragma unroll 8
        for (int kk = 0; kk < AK; kk++) {
            float a[4];
#pragma unroll
            for (int i = 0; i < 4; i++) a[i] = Ss[(ty * 4 + i) * SS_STRIDE + kk];
            float v[8];
            *(float4*)&v[0] = *(const float4*)&Vs[kk * HD_ + tx * 8];
            *(float4*)&v[4] = *(const float4*)&Vs[kk * HD_ + tx * 8 + 4];
#pragma unroll
            for (int i = 0; i < 4; i++)
#pragma unroll
                for (int j = 0; j < 8; j++)
                    o[i][j] += a[i] * v[j];
        }
    }
    __syncthreads();

    // Normalize and store to g_attn[b, s, h*128 + d]
#pragma unroll
    for (int i = 0; i < 4; i++) {
        int r = ty * 4 + i;
        float inv = 1.0f / rowl[r];
        float* dst = out + (size_t)(b * S_ + q0 + r) * QSZ + h * HD_ + tx * 8;
        *(float4*)dst       = make_float4(o[i][0] * inv, o[i][1] * inv, o[i][2] * inv, o[i][3] * inv);
        *(float4*)(dst + 4) = make_float4(o[i][4] * inv, o[i][5] * inv, o[i][6] * inv, o[i][7] * inv);
    }
}

// ============================================================================
// kernel_launch
// ============================================================================
extern "C" void kernel_launch(void* const* d_in, const int* in_sizes, int n_in,
                              void* d_out, int out_size) {
    const float* hs    = (const float*)d_in[0];
    const float* cosb  = (const float*)d_in[1];
    const float* sinb  = (const float*)d_in[2];
    const float* w_qkv = (const float*)d_in[3];
    const float* w_o   = (const float*)d_in[4];
    float* out = (float*)d_out;

    float* qkv;  cudaGetSymbolAddress((void**)&qkv,  g_qkv);
    float* attn; cudaGetSymbolAddress((void**)&attn, g_attn);

    cudaFuncSetAttribute(attn_kernel, cudaFuncAttributeMaxDynamicSharedMemorySize,
                         ATTN_SMEM_BYTES);

    // 1) QKV projection: [4096,4096] x [6144,4096]^T -> [4096,6144]
    {
        dim3 grid(OSZ / GBN, TOK / GBM);
        gemm_nt<<<grid, 256>>>(hs, w_qkv, qkv, TOK, OSZ, HID_);
    }

    // 2) RoPE in place on Q and K
    {
        int total = TOK * (NH_ + NKV_) * 64;
        rope_kernel<<<total / 256, 256>>>(qkv, cosb, sinb);
    }

    // 3) Attention
    {
        dim3 grid(S_ / AQ, B_ * NH_);
        attn_kernel<<<grid, 256, ATTN_SMEM_BYTES>>>(qkv, attn);
    }

    // 4) Output projection: [4096,4096] x [4096,4096]^T -> [4096,4096]
    {
        dim3 grid(HID_ / GBN, TOK / GBM);
        gemm_nt<<<grid, 256>>>(attn, w_o, out, TOK, HID_, QSZ);
    }
}

// round 4
// speedup vs baseline: 1.7044x; 1.7044x over previous
#include <cuda_runtime.h>
#include <cuda_bf16.h>
#include <cstdint>

// ===== Problem constants =====
#define B_    2
#define S_    2048
#define HID_  4096
#define NH_   32
#define NKV_  8
#define HD_   128
#define QSZ   (NH_ * HD_)
#define KVSZ  (NKV_ * HD_)
#define OSZ   (QSZ + 2 * KVSZ)     // 6144
#define TOK   (B_ * S_)            // 4096

__device__ float g_qkv[TOK * OSZ];
__device__ float g_attn[TOK * QSZ];

// ============================================================================
// mma.sync helpers (sm_80+ path, works on plain sm_100 target)
// ============================================================================
__device__ __forceinline__ uint32_t smem_u32(const void* p) {
    uint32_t a;
    asm("{ .reg .u64 t; cvta.to.shared.u64 t, %1; cvt.u32.u64 %0, t; }" : "=r"(a) : "l"(p));
    return a;
}
__device__ __forceinline__ void ldmatrix_x4(uint32_t& r0, uint32_t& r1,
                                            uint32_t& r2, uint32_t& r3, uint32_t addr) {
    asm volatile("ldmatrix.sync.aligned.m8n8.x4.shared.b16 {%0,%1,%2,%3}, [%4];"
                 : "=r"(r0), "=r"(r1), "=r"(r2), "=r"(r3) : "r"(addr));
}
__device__ __forceinline__ void mma_bf16(float* d, const uint32_t* a, uint32_t b0, uint32_t b1) {
    asm volatile(
        "mma.sync.aligned.m16n8k16.row.col.f32.bf16.bf16.f32 "
        "{%0,%1,%2,%3}, {%4,%5,%6,%7}, {%8,%9}, {%0,%1,%2,%3};"
        : "+f"(d[0]), "+f"(d[1]), "+f"(d[2]), "+f"(d[3])
        : "r"(a[0]), "r"(a[1]), "r"(a[2]), "r"(a[3]), "r"(b0), "r"(b1));
}

// ============================================================================
// Tensor-core GEMM: C[M,N] = A[M,K] * Bw[N,K]^T, fp32 via bf16 hi/lo 3-pass.
// 128x128x32 CTA tile, 256 threads (8 warps: 4m x 2n), double-buffered smem.
// Smem rows: 32 data bf16 + 8 pad = stride 40 elems (80B) -> conflict-free ldmatrix.
// ============================================================================
#define BK      32
#define ROWSTR  40                 // elements
#define MAT_B   (128 * ROWSTR * 2) // 10240 bytes per matrix
#define STAGE_B (4 * MAT_B)        // Ah, Al, Bh, Bl
#define GEMM_SMEM_BYTES (2 * STAGE_B)

__global__ __launch_bounds__(256, 1) void gemm_mma(const float* __restrict__ A,
                                                   const float* __restrict__ Bw,
                                                   float* __restrict__ C,
                                                   int N, int K, int nBlkN) {
    extern __shared__ char sm[];
    const uint32_t sbase = smem_u32(sm);

    // grouped rasterization: 8 M-blocks per group for L2 reuse
    int lin = blockIdx.x;
    int grp = lin / (8 * nBlkN);
    int rem = lin - grp * (8 * nBlkN);
    int bm  = grp * 8 + (rem & 7);
    int bn  = rem >> 3;

    const int t    = threadIdx.x;
    const int lane = t & 31;
    const int wid  = t >> 5;
    const int wm   = wid & 3;      // 0..3 -> 32-row slice
    const int wn   = wid >> 2;     // 0..1 -> 64-col slice

    const float* Ab = A  + (size_t)bm * 128 * K;
    const float* Bb = Bw + (size_t)bn * 128 * K;

    // per-thread global load mapping: 4 float4 per matrix per chunk
    const int ldRow = t >> 3;          // 0..31 (x4 iterations -> 128 rows)
    const int ldC4  = (t & 7) * 4;     // 0..28

    float acc[2][8][4];
#pragma unroll
    for (int i = 0; i < 2; i++)
#pragma unroll
        for (int j = 0; j < 8; j++)
#pragma unroll
            for (int k = 0; k < 4; k++) acc[i][j][k] = 0.0f;

    float4 stA[4], stB[4];

    auto ldg = [&](int k0) {
#pragma unroll
        for (int i = 0; i < 4; i++) {
            int r = ldRow + i * 32;
            stA[i] = *(const float4*)(Ab + (size_t)r * K + k0 + ldC4);
            stB[i] = *(const float4*)(Bb + (size_t)r * K + k0 + ldC4);
        }
    };
    auto cvt_sts = [&](int st) {
        char* base = sm + st * STAGE_B;
        __nv_bfloat16* ah = (__nv_bfloat16*)(base);
        __nv_bfloat16* al = (__nv_bfloat16*)(base + MAT_B);
        __nv_bfloat16* bh = (__nv_bfloat16*)(base + 2 * MAT_B);
        __nv_bfloat16* bl = (__nv_bfloat16*)(base + 3 * MAT_B);
#pragma unroll
        for (int i = 0; i < 4; i++) {
            int r = ldRow + i * 32;
            int o = r * ROWSTR + ldC4;
            {
                float4 v = stA[i];
                __nv_bfloat162 h01 = __floats2bfloat162_rn(v.x, v.y);
                __nv_bfloat162 h23 = __floats2bfloat162_rn(v.z, v.w);
                *(uint2*)(ah + o) = make_uint2(*(uint32_t*)&h01, *(uint32_t*)&h23);
                __nv_bfloat162 l01 = __floats2bfloat162_rn(v.x - __bfloat162float(h01.x),
                                                           v.y - __bfloat162float(h01.y));
                __nv_bfloat162 l23 = __floats2bfloat162_rn(v.z - __bfloat162float(h23.x),
                                                           v.w - __bfloat162float(h23.y));
                *(uint2*)(al + o) = make_uint2(*(uint32_t*)&l01, *(uint32_t*)&l23);
            }
            {
                float4 v = stB[i];
                __nv_bfloat162 h01 = __floats2bfloat162_rn(v.x, v.y);
                __nv_bfloat162 h23 = __floats2bfloat162_rn(v.z, v.w);
                *(uint2*)(bh + o) = make_uint2(*(uint32_t*)&h01, *(uint32_t*)&h23);
                __nv_bfloat162 l01 = __floats2bfloat162_rn(v.x - __bfloat162float(h01.x),
                                                           v.y - __bfloat162float(h01.y));
                __nv_bfloat162 l23 = __floats2bfloat162_rn(v.z - __bfloat162float(h23.x),
                                                           v.w - __bfloat162float(h23.y));
                *(uint2*)(bl + o) = make_uint2(*(uint32_t*)&l01, *(uint32_t*)&l23);
            }
        }
    };

    auto compute = [&](int st) {
        const uint32_t base = sbase + st * STAGE_B;
        const uint32_t aRowOff = (uint32_t)((wm * 32 + (lane & 15)) * ROWSTR + (lane >> 4) * 8) * 2;
        const uint32_t bRowOff = (uint32_t)((wn * 64 + (lane & 15)) * ROWSTR + (lane >> 4) * 8) * 2;
#pragma unroll
        for (int kk = 0; kk < 2; kk++) {
            const uint32_t ko = (uint32_t)(kk * 16) * 2;
            uint32_t ahf[2][4], alf[2][4];
#pragma unroll
            for (int mt = 0; mt < 2; mt++) {
                uint32_t off = aRowOff + (uint32_t)(mt * 16 * ROWSTR) * 2 + ko;
                ldmatrix_x4(ahf[mt][0], ahf[mt][1], ahf[mt][2], ahf[mt][3], base + off);
                ldmatrix_x4(alf[mt][0], alf[mt][1], alf[mt][2], alf[mt][3], base + MAT_B + off);
            }
            uint32_t bhf[4][4], blf[4][4];
#pragma unroll
            for (int g = 0; g < 4; g++) {
                uint32_t off = bRowOff + (uint32_t)(g * 16 * ROWSTR) * 2 + ko;
                ldmatrix_x4(bhf[g][0], bhf[g][1], bhf[g][2], bhf[g][3], base + 2 * MAT_B + off);
                ldmatrix_x4(blf[g][0], blf[g][1], blf[g][2], blf[g][3], base + 3 * MAT_B + off);
            }
#pragma unroll
            for (int mt = 0; mt < 2; mt++) {
#pragma unroll
                for (int g = 0; g < 4; g++) {
                    // n-tile 2g: frag {r0, r2}; n-tile 2g+1: frag {r1, r3}
                    mma_bf16(acc[mt][2 * g],     ahf[mt], bhf[g][0], bhf[g][2]);
                    mma_bf16(acc[mt][2 * g],     ahf[mt], blf[g][0], blf[g][2]);
                    mma_bf16(acc[mt][2 * g],     alf[mt], bhf[g][0], bhf[g][2]);
                    mma_bf16(acc[mt][2 * g + 1], ahf[mt], bhf[g][1], bhf[g][3]);
                    mma_bf16(acc[mt][2 * g + 1], ahf[mt], blf[g][1], blf[g][3]);
                    mma_bf16(acc[mt][2 * g + 1], alf[mt], bhf[g][1], bhf[g][3]);
                }
            }
        }
    };

    const int nchunk = K / BK;
    ldg(0);
    cvt_sts(0);
    __syncthreads();
    for (int c = 0; c < nchunk; c++) {
        const int cur = c & 1;
        if (c + 1 < nchunk) ldg((c + 1) * BK);
        compute(cur);
        if (c + 1 < nchunk) cvt_sts(cur ^ 1);
        __syncthreads();
    }

    // epilogue: write accumulators
    const int rowBase = bm * 128 + wm * 32 + (lane >> 2);
    const int colBase = bn * 128 + wn * 64 + (lane & 3) * 2;
#pragma unroll
    for (int mt = 0; mt < 2; mt++) {
#pragma unroll
        for (int nt = 0; nt < 8; nt++) {
            float* c0 = C + (size_t)(rowBase + mt * 16) * N + colBase + nt * 8;
            *(float2*)c0                     = make_float2(acc[mt][nt][0], acc[mt][nt][1]);
            *(float2*)(c0 + (size_t)8 * N)   = make_float2(acc[mt][nt][2], acc[mt][nt][3]);
        }
    }
}

// ============================================================================
// RoPE (unchanged)
// ============================================================================
__global__ __launch_bounds__(256) void rope_kernel(float* __restrict__ qkv,
                                                   const float* __restrict__ cosb,
                                                   const float* __restrict__ sinb) {
    int p = blockIdx.x * blockDim.x + threadIdx.x;
    int d    = p & 63;
    int rest = p >> 6;
    int hh   = rest % (NH_ + NKV_);
    int bs   = rest / (NH_ + NKV_);
    if (bs >= TOK) return;

    size_t base = (size_t)bs * OSZ;
    int off = (hh < NH_) ? (hh * HD_) : (QSZ + (hh - NH_) * HD_);

    float x1 = qkv[base + off + d];
    float x2 = qkv[base + off + d + 64];
    size_t cb = (size_t)bs * HD_;
    float c1 = cosb[cb + d],      s1 = sinb[cb + d];
    float c2 = cosb[cb + d + 64], s2 = sinb[cb + d + 64];

    qkv[base + off + d]      = x1 * c1 - x2 * s1;
    qkv[base + off + d + 64] = x2 * c2 + x1 * s2;
}

// ============================================================================
// Flash attention, fp32 (unchanged — known passing)
// ============================================================================
#define AQ 64
#define AK 64
#define QT_STRIDE 68
#define SS_STRIDE 68
#define ATTN_SMEM_FLOATS (HD_ * QT_STRIDE + HD_ * QT_STRIDE + AQ * SS_STRIDE + 3 * AQ)
#define ATTN_SMEM_BYTES  (ATTN_SMEM_FLOATS * 4)

__global__ __launch_bounds__(256) void attn_kernel(const float* __restrict__ qkv,
                                                   float* __restrict__ out) {
    extern __shared__ float smf[];
    float* Qt   = smf;
    float* Kt   = Qt + HD_ * QT_STRIDE;
    float* Vs   = Kt;
    float* Ss   = Kt + HD_ * QT_STRIDE;
    float* rowm = Ss + AQ * SS_STRIDE;
    float* rowl = rowm + AQ;
    float* rowf = rowl + AQ;

    const int qt = (int)gridDim.x - 1 - (int)blockIdx.x;
    const int bh = blockIdx.y;
    const int b  = bh >> 5;
    const int h  = bh & 31;
    const int kvh = h >> 2;

    const float* qbase = qkv + (size_t)b * S_ * OSZ + h * HD_;
    const float* kbase = qkv + (size_t)b * S_ * OSZ + QSZ + kvh * HD_;
    const float* vbase = kbase + KVSZ;

    const int t  = threadIdx.x;
    const int tx = t & 15;
    const int ty = t >> 4;
    const int q0 = qt * AQ;

    const float scaling = 0.08838834764831843f;

#pragma unroll
    for (int i = 0; i < 8; i++) {
        int idx = t + i * 256;
        int r   = idx >> 5;
        int c4  = (idx & 31) * 4;
        float4 v = *(const float4*)(qbase + (size_t)(q0 + r) * OSZ + c4);
        Qt[(c4 + 0) * QT_STRIDE + r] = v.x;
        Qt[(c4 + 1) * QT_STRIDE + r] = v.y;
        Qt[(c4 + 2) * QT_STRIDE + r] = v.z;
        Qt[(c4 + 3) * QT_STRIDE + r] = v.w;
    }
    if (t < AQ) { rowm[t] = -1e30f; rowl[t] = 0.0f; }

    float o[4][8];
#pragma unroll
    for (int i = 0; i < 4; i++)
#pragma unroll
        for (int j = 0; j < 8; j++) o[i][j] = 0.0f;

    const int ntiles = qt + 1;
    for (int kt = 0; kt < ntiles; kt++) {
        const int k0 = kt * AK;
        __syncthreads();

#pragma unroll
        for (int i = 0; i < 8; i++) {
            int idx = t + i * 256;
            int r   = idx >> 5;
            int c4  = (idx & 31) * 4;
            float4 v = *(const float4*)(kbase + (size_t)(k0 + r) * OSZ + c4);
            Kt[(c4 + 0) * QT_STRIDE + r] = v.x;
            Kt[(c4 + 1) * QT_STRIDE + r] = v.y;
            Kt[(c4 + 2) * QT_STRIDE + r] = v.z;
            Kt[(c4 + 3) * QT_STRIDE + r] = v.w;
        }
        __syncthreads();

        float s[4][4];
#pragma unroll
        for (int i = 0; i < 4; i++)
#pragma unroll
            for (int j = 0; j < 4; j++) s[i][j] = 0.0f;

#pragma unroll 8
        for (int kk = 0; kk < HD_; kk++) {
            float a[4], bf[4];
            *(float4*)a  = *(const float4*)&Qt[kk * QT_STRIDE + ty * 4];
            *(float4*)bf = *(const float4*)&Kt[kk * QT_STRIDE + tx * 4];
#pragma unroll
            for (int i = 0; i < 4; i++)
#pragma unroll
                for (int j = 0; j < 4; j++)
                    s[i][j] += a[i] * bf[j];
        }

        const bool diag = (kt == qt);
#pragma unroll
        for (int i = 0; i < 4; i++) {
            int r = ty * 4 + i;
#pragma unroll
            for (int j = 0; j < 4; j++) {
                int c = tx * 4 + j;
                float v = s[i][j] * scaling;
                if (diag && (k0 + c > q0 + r)) v = -1e30f;
                Ss[r * SS_STRIDE + c] = v;
            }
        }
        __syncthreads();

#pragma unroll
        for (int i = 0; i < 8; i++) {
            int idx = t + i * 256;
            int r   = idx >> 5;
            int c4  = (idx & 31) * 4;
            *(float4*)&Vs[r * HD_ + c4] =
                *(const float4*)(vbase + (size_t)(k0 + r) * OSZ + c4);
        }

        {
            int r   = t >> 2;
            int seg = (t & 3) * 16;
            float mOld = rowm[r];
            float mx = mOld;
#pragma unroll
            for (int j = 0; j < 16; j++)
                mx = fmaxf(mx, Ss[r * SS_STRIDE + seg + j]);
            mx = fmaxf(mx, __shfl_xor_sync(0xFFFFFFFFu, mx, 1));
            mx = fmaxf(mx, __shfl_xor_sync(0xFFFFFFFFu, mx, 2));
            float sum = 0.0f;
#pragma unroll
            for (int j = 0; j < 16; j++) {
                float p = __expf(Ss[r * SS_STRIDE + seg + j] - mx);
                Ss[r * SS_STRIDE + seg + j] = p;
                sum += p;
            }
            sum += __shfl_xor_sync(0xFFFFFFFFu, sum, 1);
            sum += __shfl_xor_sync(0xFFFFFFFFu, sum, 2);
            if ((t & 3) == 0) {
                float f = __expf(mOld - mx);
                rowl[r] = rowl[r] * f + sum;
                rowm[r] = mx;
                rowf[r] = f;
            }
        }
        __syncthreads();

#pragma unroll
        for (int i = 0; i < 4; i++) {
            float f = rowf[ty * 4 + i];
#pragma unroll
            for (int j = 0; j < 8; j++) o[i][j] *= f;
        }

#pragma unroll 8
        for (int kk = 0; kk < AK; kk++) {
            float a[4];
#pragma unroll
            for (int i = 0; i < 4; i++) a[i] = Ss[(ty * 4 + i) * SS_STRIDE + kk];
            float v[8];
            *(float4*)&v[0] = *(const float4*)&Vs[kk * HD_ + tx * 8];
            *(float4*)&v[4] = *(const float4*)&Vs[kk * HD_ + tx * 8 + 4];
#pragma unroll
            for (int i = 0; i < 4; i++)
#pragma unroll
                for (int j = 0; j < 8; j++)
                    o[i][j] += a[i] * v[j];
        }
    }
    __syncthreads();

#pragma unroll
    for (int i = 0; i < 4; i++) {
        int r = ty * 4 + i;
        float inv = 1.0f / rowl[r];
        float* dst = out + (size_t)(b * S_ + q0 + r) * QSZ + h * HD_ + tx * 8;
        *(float4*)dst       = make_float4(o[i][0] * inv, o[i][1] * inv, o[i][2] * inv, o[i][3] * inv);
        *(float4*)(dst + 4) = make_float4(o[i][4] * inv, o[i][5] * inv, o[i][6] * inv, o[i][7] * inv);
    }
}

// ============================================================================
// kernel_launch
// ============================================================================
extern "C" void kernel_launch(void* const* d_in, const int* in_sizes, int n_in,
                              void* d_out, int out_size) {
    const float* hs    = (const float*)d_in[0];
    const float* cosb  = (const float*)d_in[1];
    const float* sinb  = (const float*)d_in[2];
    const float* w_qkv = (const float*)d_in[3];
    const float* w_o   = (const float*)d_in[4];
    float* out = (float*)d_out;

    float* qkv;  cudaGetSymbolAddress((void**)&qkv,  g_qkv);
    float* attn; cudaGetSymbolAddress((void**)&attn, g_attn);

    cudaFuncSetAttribute(gemm_mma, cudaFuncAttributeMaxDynamicSharedMemorySize, GEMM_SMEM_BYTES);
    cudaFuncSetAttribute(attn_kernel, cudaFuncAttributeMaxDynamicSharedMemorySize, ATTN_SMEM_BYTES);

    // 1) QKV projection: [4096,4096] x [6144,4096]^T -> [4096,6144]
    {
        int nBlkN = OSZ / 128, nBlkM = TOK / 128;
        gemm_mma<<<nBlkM * nBlkN, 256, GEMM_SMEM_BYTES>>>(hs, w_qkv, qkv, OSZ, HID_, nBlkN);
    }
    // 2) RoPE
    {
        int total = TOK * (NH_ + NKV_) * 64;
        rope_kernel<<<total / 256, 256>>>(qkv, cosb, sinb);
    }
    // 3) Attention
    {
        dim3 grid(S_ / AQ, B_ * NH_);
        attn_kernel<<<grid, 256, ATTN_SMEM_BYTES>>>(qkv, attn);
    }
    // 4) Output projection: [4096,4096] x [4096,4096]^T -> [4096,4096]
    {
        int nBlkN = HID_ / 128, nBlkM = TOK / 128;
        gemm_mma<<<nBlkM * nBlkN, 256, GEMM_SMEM_BYTES>>>(attn, w_o, out, HID_, QSZ, nBlkN);
    }
}

// round 5
// speedup vs baseline: 2.5858x; 1.5171x over previous
#include <cuda_runtime.h>
#include <cuda_bf16.h>
#include <cstdint>

// ===== Problem constants =====
#define B_    2
#define S_    2048
#define HID_  4096
#define NH_   32
#define NKV_  8
#define HD_   128
#define QSZ   (NH_ * HD_)
#define KVSZ  (NKV_ * HD_)
#define OSZ   (QSZ + 2 * KVSZ)     // 6144
#define TOK   (B_ * S_)            // 4096
#define SCALING 0.08838834764831843f

// ===== Scratch =====
__device__ float g_qkv[TOK * OSZ];                  // fp32 QKV (rope in place)
__device__ __nv_bfloat16 g_hsh[TOK * HID_],  g_hsl[TOK * HID_];
__device__ __nv_bfloat16 g_wqh[OSZ * HID_],  g_wql[OSZ * HID_];
__device__ __nv_bfloat16 g_woh[HID_ * QSZ],  g_wol[HID_ * QSZ];
__device__ __nv_bfloat16 g_ath[TOK * QSZ],   g_atl[TOK * QSZ];

// ============================================================================
// PTX helpers
// ============================================================================
__device__ __forceinline__ uint32_t smem_u32(const void* p) {
    uint32_t a;
    asm("{ .reg .u64 t; cvta.to.shared.u64 t, %1; cvt.u32.u64 %0, t; }" : "=r"(a) : "l"(p));
    return a;
}
__device__ __forceinline__ void ldmatrix_x4(uint32_t& r0, uint32_t& r1,
                                            uint32_t& r2, uint32_t& r3, uint32_t addr) {
    asm volatile("ldmatrix.sync.aligned.m8n8.x4.shared.b16 {%0,%1,%2,%3}, [%4];"
                 : "=r"(r0), "=r"(r1), "=r"(r2), "=r"(r3) : "r"(addr));
}
__device__ __forceinline__ void ldmatrix_x4t(uint32_t& r0, uint32_t& r1,
                                             uint32_t& r2, uint32_t& r3, uint32_t addr) {
    asm volatile("ldmatrix.sync.aligned.m8n8.x4.trans.shared.b16 {%0,%1,%2,%3}, [%4];"
                 : "=r"(r0), "=r"(r1), "=r"(r2), "=r"(r3) : "r"(addr));
}
__device__ __forceinline__ void mma_bf16(float* d, const uint32_t* a, uint32_t b0, uint32_t b1) {
    asm volatile(
        "mma.sync.aligned.m16n8k16.row.col.f32.bf16.bf16.f32 "
        "{%0,%1,%2,%3}, {%4,%5,%6,%7}, {%8,%9}, {%0,%1,%2,%3};"
        : "+f"(d[0]), "+f"(d[1]), "+f"(d[2]), "+f"(d[3])
        : "r"(a[0]), "r"(a[1]), "r"(a[2]), "r"(a[3]), "r"(b0), "r"(b1));
}
__device__ __forceinline__ void cp_async16(uint32_t s, const void* g) {
    asm volatile("cp.async.cg.shared.global [%0], [%1], 16;" :: "r"(s), "l"(g) : "memory");
}
#define CP_COMMIT() asm volatile("cp.async.commit_group;" ::: "memory")
#define CP_WAIT1()  asm volatile("cp.async.wait_group 1;" ::: "memory")
#define CP_WAIT0()  asm volatile("cp.async.wait_group 0;" ::: "memory")

__device__ __forceinline__ uint32_t pack_hi(float a, float b) {
    __nv_bfloat162 h = __floats2bfloat162_rn(a, b);
    return *(uint32_t*)&h;
}
__device__ __forceinline__ uint32_t pack_lo(float a, float b, uint32_t hi) {
    __nv_bfloat162 h = *(__nv_bfloat162*)&hi;
    __nv_bfloat162 l = __floats2bfloat162_rn(a - __bfloat162float(h.x),
                                             b - __bfloat162float(h.y));
    return *(uint32_t*)&l;
}

// ============================================================================
// split kernel: fp32 array -> (hi, lo) bf16 arrays
// ============================================================================
__global__ __launch_bounds__(256) void split_kernel(const float* __restrict__ in,
                                                    __nv_bfloat16* __restrict__ hi,
                                                    __nv_bfloat16* __restrict__ lo, int n4) {
    int i = blockIdx.x * blockDim.x + threadIdx.x;
    if (i >= n4) return;
    float4 v = ((const float4*)in)[i];
    uint32_t h01 = pack_hi(v.x, v.y), h23 = pack_hi(v.z, v.w);
    ((uint2*)hi)[i] = make_uint2(h01, h23);
    ((uint2*)lo)[i] = make_uint2(pack_lo(v.x, v.y, h01), pack_lo(v.z, v.w, h23));
}

// ============================================================================
// bf16 3-pass GEMM: C[M,N] = (Ah+Al)[M,K] * (Bh+Bl)[N,K]^T (drop Al*Bl)
// 128x128x64 tile, 256 threads, cp.async 3-stage pipeline.
// ============================================================================
#define GBK    64
#define GSTR   72                    // bf16 elems per smem row (64 data + 8 pad)
#define GMATB  (128 * GSTR * 2)      // 18432 B
#define GSTAGEB (4 * GMATB)          // 73728 B
#define GEMM_SMEM (3 * GSTAGEB)      // 221184 B

__global__ __launch_bounds__(256, 1) void gemm_bf3(const __nv_bfloat16* __restrict__ Ah,
                                                   const __nv_bfloat16* __restrict__ Al,
                                                   const __nv_bfloat16* __restrict__ Bh,
                                                   const __nv_bfloat16* __restrict__ Bl,
                                                   float* __restrict__ C,
                                                   int N, int K, int nBlkN) {
    extern __shared__ char sm[];
    const uint32_t sb = smem_u32(sm);

    int lin = blockIdx.x;
    int grp = lin / (8 * nBlkN);
    int rem = lin - grp * (8 * nBlkN);
    int bm  = grp * 8 + (rem & 7);
    int bn  = rem >> 3;

    const int t = threadIdx.x, lane = t & 31, wid = t >> 5;
    const int wm = wid & 3, wn = wid >> 2;

    const __nv_bfloat16* mats[4] = {
        Ah + (size_t)bm * 128 * K, Al + (size_t)bm * 128 * K,
        Bh + (size_t)bn * 128 * K, Bl + (size_t)bn * 128 * K };

    float acc[2][8][4];
#pragma unroll
    for (int i = 0; i < 2; i++)
#pragma unroll
        for (int j = 0; j < 8; j++)
#pragma unroll
            for (int k = 0; k < 4; k++) acc[i][j][k] = 0.0f;

    const int nchunk = K / GBK;

    auto issue = [&](int g) {
        const int s = g % 3;
        const uint32_t stg = sb + s * GSTAGEB;
        const int k0 = g * GBK;
#pragma unroll
        for (int m = 0; m < 4; m++) {
            const __nv_bfloat16* src = mats[m] + k0;
            const uint32_t dstm = stg + m * GMATB;
#pragma unroll
            for (int i = 0; i < 4; i++) {
                int id  = t + i * 256;         // 0..1023
                int row = id >> 3, c = id & 7;
                cp_async16(dstm + (uint32_t)(row * GSTR + c * 8) * 2,
                           src + (size_t)row * K + c * 8);
            }
        }
        CP_COMMIT();
    };

    auto compute = [&](int st) {
        const uint32_t base = sb + st * GSTAGEB;
        const uint32_t aOff = (uint32_t)((wm * 32 + (lane & 15)) * GSTR + (lane >> 4) * 8) * 2;
        const uint32_t bOff = (uint32_t)((wn * 64 + (lane & 15)) * GSTR + (lane >> 4) * 8) * 2;
#pragma unroll
        for (int kk = 0; kk < 4; kk++) {
            const uint32_t ko = (uint32_t)(kk * 16) * 2;
            uint32_t ahf[2][4], alf[2][4];
#pragma unroll
            for (int mt = 0; mt < 2; mt++) {
                uint32_t off = aOff + (uint32_t)(mt * 16 * GSTR) * 2 + ko;
                ldmatrix_x4(ahf[mt][0], ahf[mt][1], ahf[mt][2], ahf[mt][3], base + off);
                ldmatrix_x4(alf[mt][0], alf[mt][1], alf[mt][2], alf[mt][3], base + GMATB + off);
            }
            uint32_t bhf[4][4], blf[4][4];
#pragma unroll
            for (int g = 0; g < 4; g++) {
                uint32_t off = bOff + (uint32_t)(g * 16 * GSTR) * 2 + ko;
                ldmatrix_x4(bhf[g][0], bhf[g][1], bhf[g][2], bhf[g][3], base + 2 * GMATB + off);
                ldmatrix_x4(blf[g][0], blf[g][1], blf[g][2], blf[g][3], base + 3 * GMATB + off);
            }
#pragma unroll
            for (int mt = 0; mt < 2; mt++) {
#pragma unroll
                for (int g = 0; g < 4; g++) {
                    mma_bf16(acc[mt][2 * g],     ahf[mt], bhf[g][0], bhf[g][2]);
                    mma_bf16(acc[mt][2 * g],     ahf[mt], blf[g][0], blf[g][2]);
                    mma_bf16(acc[mt][2 * g],     alf[mt], bhf[g][0], bhf[g][2]);
                    mma_bf16(acc[mt][2 * g + 1], ahf[mt], bhf[g][1], bhf[g][3]);
                    mma_bf16(acc[mt][2 * g + 1], ahf[mt], blf[g][1], blf[g][3]);
                    mma_bf16(acc[mt][2 * g + 1], alf[mt], bhf[g][1], bhf[g][3]);
                }
            }
        }
    };

    issue(0);
    issue(1);
    for (int c = 0; c < nchunk; c++) {
        if (c >= nchunk - 2) { CP_WAIT0(); } else { CP_WAIT1(); }
        __syncthreads();
        if (c + 2 < nchunk) issue(c + 2);
        compute(c % 3);
    }

    const int rowBase = bm * 128 + wm * 32 + (lane >> 2);
    const int colBase = bn * 128 + wn * 64 + (lane & 3) * 2;
#pragma unroll
    for (int mt = 0; mt < 2; mt++) {
#pragma unroll
        for (int nt = 0; nt < 8; nt++) {
            float* c0 = C + (size_t)(rowBase + mt * 16) * N + colBase + nt * 8;
            *(float2*)c0                   = make_float2(acc[mt][nt][0], acc[mt][nt][1]);
            *(float2*)(c0 + (size_t)8 * N) = make_float2(acc[mt][nt][2], acc[mt][nt][3]);
        }
    }
}

// ============================================================================
// RoPE (fp32, in place on g_qkv)
// ============================================================================
__global__ __launch_bounds__(256) void rope_kernel(float* __restrict__ qkv,
                                                   const float* __restrict__ cosb,
                                                   const float* __restrict__ sinb) {
    int p = blockIdx.x * blockDim.x + threadIdx.x;
    int d    = p & 63;
    int rest = p >> 6;
    int hh   = rest % (NH_ + NKV_);
    int bs   = rest / (NH_ + NKV_);
    if (bs >= TOK) return;

    size_t base = (size_t)bs * OSZ;
    int off = (hh < NH_) ? (hh * HD_) : (QSZ + (hh - NH_) * HD_);

    float x1 = qkv[base + off + d];
    float x2 = qkv[base + off + d + 64];
    size_t cb = (size_t)bs * HD_;
    float c1 = cosb[cb + d],      s1 = sinb[cb + d];
    float c2 = cosb[cb + d + 64], s2 = sinb[cb + d + 64];

    qkv[base + off + d]      = x1 * c1 - x2 * s1;
    qkv[base + off + d + 64] = x2 * c2 + x1 * s2;
}

// ============================================================================
// Tensor-core flash attention.
// Q tile 128 x KV tile 64, 8 warps (16 q-rows each), bf16 hi/lo 3-pass for
// QK and PV; softmax fp32 in fragments. Output written as bf16 hi/lo.
// ============================================================================
#define ASTR 136                     // bf16 elems per smem row
#define AQB  (128 * ASTR * 2)        // 34816 B (Q matrix)
#define AKB  (64 * ASTR * 2)         // 17408 B (K/V matrix)
#define OFF_QH 0
#define OFF_QL (AQB)
#define OFF_KH (2 * AQB)
#define OFF_KL (2 * AQB + AKB)
#define OFF_VH (2 * AQB + 2 * AKB)
#define OFF_VL (2 * AQB + 3 * AKB)
#define ATTN_SMEM (2 * AQB + 4 * AKB)   // 139264 B

__global__ __launch_bounds__(256, 1) void attn_tc(const float* __restrict__ qkv,
                                                  __nv_bfloat16* __restrict__ outh,
                                                  __nv_bfloat16* __restrict__ outl) {
    extern __shared__ char sm[];
    const uint32_t sb = smem_u32(sm);

    const int qt = (int)gridDim.x - 1 - (int)blockIdx.x;
    const int bh = blockIdx.y;
    const int b  = bh >> 5;
    const int h  = bh & 31;
    const int kvh = h >> 2;

    const float* qbase = qkv + (size_t)b * S_ * OSZ + h * HD_;
    const float* kbase = qkv + (size_t)b * S_ * OSZ + QSZ + kvh * HD_;
    const float* vbase = kbase + KVSZ;

    const int t = threadIdx.x, lane = t & 31, wid = t >> 5;
    const int q0 = qt * 128;
    const int wRow = wid * 16;          // warp's q-row base within tile

    // ---- load Q tile, fold scaling, split hi/lo into smem ----
#pragma unroll
    for (int i = 0; i < 16; i++) {
        int idx = t + i * 256;          // 0..4095
        int r   = idx >> 5;             // 0..127
        int c4  = (idx & 31) * 4;       // 0..124
        float4 v = *(const float4*)(qbase + (size_t)(q0 + r) * OSZ + c4);
        v.x *= SCALING; v.y *= SCALING; v.z *= SCALING; v.w *= SCALING;
        uint32_t h01 = pack_hi(v.x, v.y), h23 = pack_hi(v.z, v.w);
        uint32_t off = (uint32_t)(r * ASTR + c4) * 2;
        *(uint2*)(sm + OFF_QH + off) = make_uint2(h01, h23);
        *(uint2*)(sm + OFF_QL + off) = make_uint2(pack_lo(v.x, v.y, h01), pack_lo(v.z, v.w, h23));
    }

    float m0 = -1e30f, m1 = -1e30f, l0 = 0.0f, l1 = 0.0f;
    float o[16][4];
#pragma unroll
    for (int i = 0; i < 16; i++)
#pragma unroll
        for (int j = 0; j < 4; j++) o[i][j] = 0.0f;

    const int nkv = qt * 2 + 2;
    for (int kt = 0; kt < nkv; kt++) {
        const int k0 = kt * 64;

        // stage K,V (fp32) into registers
        float4 stg[16];
        {
            int r  = t >> 5;            // 0..7 base row (+8 per i)
            int c4 = (t & 31) * 4;
#pragma unroll
            for (int i = 0; i < 8; i++)
                stg[i] = *(const float4*)(kbase + (size_t)(k0 + r + i * 8) * OSZ + c4);
#pragma unroll
            for (int i = 0; i < 8; i++)
                stg[8 + i] = *(const float4*)(vbase + (size_t)(k0 + r + i * 8) * OSZ + c4);
        }
        __syncthreads();                 // previous iteration done reading K/V smem
        {
            int r  = t >> 5;
            int c4 = (t & 31) * 4;
#pragma unroll
            for (int i = 0; i < 8; i++) {
                uint32_t off = (uint32_t)((r + i * 8) * ASTR + c4) * 2;
                float4 v = stg[i];
                uint32_t h01 = pack_hi(v.x, v.y), h23 = pack_hi(v.z, v.w);
                *(uint2*)(sm + OFF_KH + off) = make_uint2(h01, h23);
                *(uint2*)(sm + OFF_KL + off) = make_uint2(pack_lo(v.x, v.y, h01), pack_lo(v.z, v.w, h23));
                float4 w = stg[8 + i];
                uint32_t g01 = pack_hi(w.x, w.y), g23 = pack_hi(w.z, w.w);
                *(uint2*)(sm + OFF_VH + off) = make_uint2(g01, g23);
                *(uint2*)(sm + OFF_VL + off) = make_uint2(pack_lo(w.x, w.y, g01), pack_lo(w.z, w.w, g23));
            }
        }
        __syncthreads();

        // ---- S = Q K^T (16 x 64 per warp), 3-pass hi/lo ----
        float sacc[8][4];
#pragma unroll
        for (int i = 0; i < 8; i++)
#pragma unroll
            for (int j = 0; j < 4; j++) sacc[i][j] = 0.0f;

        const uint32_t aOff = (uint32_t)((wRow + (lane & 15)) * ASTR + (lane >> 4) * 8) * 2;
        const uint32_t bOff = (uint32_t)(((lane & 15)) * ASTR + (lane >> 4) * 8) * 2;
#pragma unroll
        for (int kk = 0; kk < 8; kk++) {
            const uint32_t ko = (uint32_t)(kk * 16) * 2;
            uint32_t qh[4], ql[4];
            ldmatrix_x4(qh[0], qh[1], qh[2], qh[3], sb + OFF_QH + aOff + ko);
            ldmatrix_x4(ql[0], ql[1], ql[2], ql[3], sb + OFF_QL + aOff + ko);
#pragma unroll
            for (int g = 0; g < 4; g++) {
                uint32_t off = bOff + (uint32_t)(g * 16 * ASTR) * 2 + ko;
                uint32_t kh[4], kl[4];
                ldmatrix_x4(kh[0], kh[1], kh[2], kh[3], sb + OFF_KH + off);
                ldmatrix_x4(kl[0], kl[1], kl[2], kl[3], sb + OFF_KL + off);
                mma_bf16(sacc[2 * g],     qh, kh[0], kh[2]);
                mma_bf16(sacc[2 * g],     qh, kl[0], kl[2]);
                mma_bf16(sacc[2 * g],     ql, kh[0], kh[2]);
                mma_bf16(sacc[2 * g + 1], qh, kh[1], kh[3]);
                mma_bf16(sacc[2 * g + 1], qh, kl[1], kl[3]);
                mma_bf16(sacc[2 * g + 1], ql, kh[1], kh[3]);
            }
        }

        // ---- causal mask ----
        const int r0 = q0 + wRow + (lane >> 2);
        const int r1 = r0 + 8;
        if (k0 + 63 > q0 + wRow) {
#pragma unroll
            for (int nt = 0; nt < 8; nt++) {
                int c = k0 + nt * 8 + (lane & 3) * 2;
                if (c     > r0) sacc[nt][0] = -1e30f;
                if (c + 1 > r0) sacc[nt][1] = -1e30f;
                if (c     > r1) sacc[nt][2] = -1e30f;
                if (c + 1 > r1) sacc[nt][3] = -1e30f;
            }
        }

        // ---- online softmax ----
        float mx0 = m0, mx1 = m1;
#pragma unroll
        for (int nt = 0; nt < 8; nt++) {
            mx0 = fmaxf(mx0, fmaxf(sacc[nt][0], sacc[nt][1]));
            mx1 = fmaxf(mx1, fmaxf(sacc[nt][2], sacc[nt][3]));
        }
        mx0 = fmaxf(mx0, __shfl_xor_sync(0xFFFFFFFFu, mx0, 1));
        mx0 = fmaxf(mx0, __shfl_xor_sync(0xFFFFFFFFu, mx0, 2));
        mx1 = fmaxf(mx1, __shfl_xor_sync(0xFFFFFFFFu, mx1, 1));
        mx1 = fmaxf(mx1, __shfl_xor_sync(0xFFFFFFFFu, mx1, 2));
        float f0 = __expf(m0 - mx0), f1 = __expf(m1 - mx1);
        float sum0 = 0.0f, sum1 = 0.0f;
#pragma unroll
        for (int nt = 0; nt < 8; nt++) {
            sacc[nt][0] = __expf(sacc[nt][0] - mx0);
            sacc[nt][1] = __expf(sacc[nt][1] - mx0);
            sacc[nt][2] = __expf(sacc[nt][2] - mx1);
            sacc[nt][3] = __expf(sacc[nt][3] - mx1);
            sum0 += sacc[nt][0] + sacc[nt][1];
            sum1 += sacc[nt][2] + sacc[nt][3];
        }
        sum0 += __shfl_xor_sync(0xFFFFFFFFu, sum0, 1);
        sum0 += __shfl_xor_sync(0xFFFFFFFFu, sum0, 2);
        sum1 += __shfl_xor_sync(0xFFFFFFFFu, sum1, 1);
        sum1 += __shfl_xor_sync(0xFFFFFFFFu, sum1, 2);
        m0 = mx0; m1 = mx1;
        l0 = l0 * f0 + sum0;
        l1 = l1 * f1 + sum1;
#pragma unroll
        for (int d = 0; d < 16; d++) {
            o[d][0] *= f0; o[d][1] *= f0; o[d][2] *= f1; o[d][3] *= f1;
        }

        // ---- O += P V (3-pass), P from registers, V via ldmatrix.trans ----
#pragma unroll
        for (int kt2 = 0; kt2 < 4; kt2++) {
            uint32_t Ph[4], Pl[4];
            Ph[0] = pack_hi(sacc[2 * kt2][0],     sacc[2 * kt2][1]);
            Pl[0] = pack_lo(sacc[2 * kt2][0],     sacc[2 * kt2][1],     Ph[0]);
            Ph[1] = pack_hi(sacc[2 * kt2][2],     sacc[2 * kt2][3]);
            Pl[1] = pack_lo(sacc[2 * kt2][2],     sacc[2 * kt2][3],     Ph[1]);
            Ph[2] = pack_hi(sacc[2 * kt2 + 1][0], sacc[2 * kt2 + 1][1]);
            Pl[2] = pack_lo(sacc[2 * kt2 + 1][0], sacc[2 * kt2 + 1][1], Ph[2]);
            Ph[3] = pack_hi(sacc[2 * kt2 + 1][2], sacc[2 * kt2 + 1][3]);
            Pl[3] = pack_lo(sacc[2 * kt2 + 1][2], sacc[2 * kt2 + 1][3], Ph[3]);

            const int kRow = kt2 * 16 + (lane & 7) + ((lane >> 4) & 1) * 8;
#pragma unroll
            for (int gd = 0; gd < 8; gd++) {
                const int nCol = gd * 16 + ((lane >> 3) & 1) * 8;
                const uint32_t off = (uint32_t)(kRow * ASTR + nCol) * 2;
                uint32_t vh[4], vl[4];
                ldmatrix_x4t(vh[0], vh[1], vh[2], vh[3], sb + OFF_VH + off);
                ldmatrix_x4t(vl[0], vl[1], vl[2], vl[3], sb + OFF_VL + off);
                mma_bf16(o[2 * gd],     Ph, vh[0], vh[2]);
                mma_bf16(o[2 * gd],     Ph, vl[0], vl[2]);
                mma_bf16(o[2 * gd],     Pl, vh[0], vh[2]);
                mma_bf16(o[2 * gd + 1], Ph, vh[1], vh[3]);
                mma_bf16(o[2 * gd + 1], Ph, vl[1], vl[3]);
                mma_bf16(o[2 * gd + 1], Pl, vh[1], vh[3]);
            }
        }
    }

    // ---- epilogue: normalize, split hi/lo, store ----
    const float i0 = 1.0f / l0, i1 = 1.0f / l1;
    const int tok0 = b * S_ + q0 + wRow + (lane >> 2);
    const int tok1 = tok0 + 8;
    const int colB = h * HD_ + (lane & 3) * 2;
#pragma unroll
    for (int d = 0; d < 16; d++) {
        int col = colB + d * 8;
        float v0 = o[d][0] * i0, v1 = o[d][1] * i0;
        float v2 = o[d][2] * i1, v3 = o[d][3] * i1;
        uint32_t h01 = pack_hi(v0, v1);
        uint32_t h23 = pack_hi(v2, v3);
        *(uint32_t*)(outh + (size_t)tok0 * QSZ + col) = h01;
        *(uint32_t*)(outl + (size_t)tok0 * QSZ + col) = pack_lo(v0, v1, h01);
        *(uint32_t*)(outh + (size_t)tok1 * QSZ + col) = h23;
        *(uint32_t*)(outl + (size_t)tok1 * QSZ + col) = pack_lo(v2, v3, h23);
    }
}

// ============================================================================
// kernel_launch
// ============================================================================
extern "C" void kernel_launch(void* const* d_in, const int* in_sizes, int n_in,
                              void* d_out, int out_size) {
    const float* hs    = (const float*)d_in[0];
    const float* cosb  = (const float*)d_in[1];
    const float* sinb  = (const float*)d_in[2];
    const float* w_qkv = (const float*)d_in[3];
    const float* w_o   = (const float*)d_in[4];
    float* out = (float*)d_out;

    float* qkv;  cudaGetSymbolAddress((void**)&qkv, g_qkv);
    __nv_bfloat16 *hsh, *hsl, *wqh, *wql, *woh, *wol, *ath, *atl;
    cudaGetSymbolAddress((void**)&hsh, g_hsh);
    cudaGetSymbolAddress((void**)&hsl, g_hsl);
    cudaGetSymbolAddress((void**)&wqh, g_wqh);
    cudaGetSymbolAddress((void**)&wql, g_wql);
    cudaGetSymbolAddress((void**)&woh, g_woh);
    cudaGetSymbolAddress((void**)&wol, g_wol);
    cudaGetSymbolAddress((void**)&ath, g_ath);
    cudaGetSymbolAddress((void**)&atl, g_atl);

    cudaFuncSetAttribute(gemm_bf3, cudaFuncAttributeMaxDynamicSharedMemorySize, GEMM_SMEM);
    cudaFuncSetAttribute(attn_tc,  cudaFuncAttributeMaxDynamicSharedMemorySize, ATTN_SMEM);

    // 0) split fp32 operands into bf16 hi/lo
    split_kernel<<<(TOK * HID_ / 4) / 256, 256>>>(hs, hsh, hsl, TOK * HID_ / 4);
    split_kernel<<<(OSZ * HID_ / 4) / 256, 256>>>(w_qkv, wqh, wql, OSZ * HID_ / 4);
    split_kernel<<<(HID_ * QSZ / 4) / 256, 256>>>(w_o, woh, wol, HID_ * QSZ / 4);

    // 1) QKV projection
    gemm_bf3<<<(TOK / 128) * (OSZ / 128), 256, GEMM_SMEM>>>(hsh, hsl, wqh, wql, qkv,
                                                            OSZ, HID_, OSZ / 128);
    // 2) RoPE
    rope_kernel<<<TOK * (NH_ + NKV_) * 64 / 256, 256>>>(qkv, cosb, sinb);

    // 3) Attention (writes bf16 hi/lo)
    {
        dim3 grid(S_ / 128, B_ * NH_);
        attn_tc<<<grid, 256, ATTN_SMEM>>>(qkv, ath, atl);
    }

    // 4) Output projection
    gemm_bf3<<<(TOK / 128) * (HID_ / 128), 256, GEMM_SMEM>>>(ath, atl, woh, wol, out,
                                                             HID_, QSZ, HID_ / 128);
}

// round 6
// speedup vs baseline: 2.6072x; 1.0083x over previous
#include <cuda_runtime.h>
#include <cuda_bf16.h>
#include <cstdint>

// ===== Problem constants =====
#define B_    2
#define S_    2048
#define HID_  4096
#define NH_   32
#define NKV_  8
#define HD_   128
#define QSZ   (NH_ * HD_)
#define KVSZ  (NKV_ * HD_)
#define OSZ   (QSZ + 2 * KVSZ)     // 6144
#define TOK   (B_ * S_)            // 4096
#define SCALING 0.08838834764831843f

// ===== Scratch =====
__device__ float g_qkv[TOK * OSZ];                  // fp32 QKV (rope in place)
__device__ __nv_bfloat16 g_hsh[TOK * HID_],  g_hsl[TOK * HID_];
__device__ __nv_bfloat16 g_wqh[OSZ * HID_],  g_wql[OSZ * HID_];
__device__ __nv_bfloat16 g_woh[HID_ * QSZ],  g_wol[HID_ * QSZ];
__device__ __nv_bfloat16 g_ath[TOK * QSZ],   g_atl[TOK * QSZ];

// ============================================================================
// PTX helpers
// ============================================================================
__device__ __forceinline__ uint32_t smem_u32(const void* p) {
    uint32_t a;
    asm("{ .reg .u64 t; cvta.to.shared.u64 t, %1; cvt.u32.u64 %0, t; }" : "=r"(a) : "l"(p));
    return a;
}
__device__ __forceinline__ void ldmatrix_x4(uint32_t& r0, uint32_t& r1,
                                            uint32_t& r2, uint32_t& r3, uint32_t addr) {
    asm volatile("ldmatrix.sync.aligned.m8n8.x4.shared.b16 {%0,%1,%2,%3}, [%4];"
                 : "=r"(r0), "=r"(r1), "=r"(r2), "=r"(r3) : "r"(addr));
}
__device__ __forceinline__ void ldmatrix_x4t(uint32_t& r0, uint32_t& r1,
                                             uint32_t& r2, uint32_t& r3, uint32_t addr) {
    asm volatile("ldmatrix.sync.aligned.m8n8.x4.trans.shared.b16 {%0,%1,%2,%3}, [%4];"
                 : "=r"(r0), "=r"(r1), "=r"(r2), "=r"(r3) : "r"(addr));
}
__device__ __forceinline__ void mma_bf16(float* d, const uint32_t* a, uint32_t b0, uint32_t b1) {
    asm volatile(
        "mma.sync.aligned.m16n8k16.row.col.f32.bf16.bf16.f32 "
        "{%0,%1,%2,%3}, {%4,%5,%6,%7}, {%8,%9}, {%0,%1,%2,%3};"
        : "+f"(d[0]), "+f"(d[1]), "+f"(d[2]), "+f"(d[3])
        : "r"(a[0]), "r"(a[1]), "r"(a[2]), "r"(a[3]), "r"(b0), "r"(b1));
}
__device__ __forceinline__ void cp_async16(uint32_t s, const void* g) {
    asm volatile("cp.async.cg.shared.global [%0], [%1], 16;" :: "r"(s), "l"(g) : "memory");
}
#define CP_COMMIT() asm volatile("cp.async.commit_group;" ::: "memory")
#define CP_WAIT1()  asm volatile("cp.async.wait_group 1;" ::: "memory")
#define CP_WAIT0()  asm volatile("cp.async.wait_group 0;" ::: "memory")

__device__ __forceinline__ uint32_t pack_hi(float a, float b) {
    __nv_bfloat162 h = __floats2bfloat162_rn(a, b);
    return *(uint32_t*)&h;
}
__device__ __forceinline__ uint32_t pack_lo(float a, float b, uint32_t hi) {
    __nv_bfloat162 h = *(__nv_bfloat162*)&hi;
    __nv_bfloat162 l = __floats2bfloat162_rn(a - __bfloat162float(h.x),
                                             b - __bfloat162float(h.y));
    return *(uint32_t*)&l;
}

// ============================================================================
// split kernel: fp32 array -> (hi, lo) bf16 arrays
// ============================================================================
__global__ __launch_bounds__(256) void split_kernel(const float* __restrict__ in,
                                                    __nv_bfloat16* __restrict__ hi,
                                                    __nv_bfloat16* __restrict__ lo, int n4) {
    int i = blockIdx.x * blockDim.x + threadIdx.x;
    if (i >= n4) return;
    float4 v = ((const float4*)in)[i];
    uint32_t h01 = pack_hi(v.x, v.y), h23 = pack_hi(v.z, v.w);
    ((uint2*)hi)[i] = make_uint2(h01, h23);
    ((uint2*)lo)[i] = make_uint2(pack_lo(v.x, v.y, h01), pack_lo(v.z, v.w, h23));
}

// ============================================================================
// bf16 3-pass GEMM: C[M,N] = (Ah+Al)[M,K] * (Bh+Bl)[N,K]^T (drop Al*Bl)
// 128x128x64 tile, 512 threads (16 warps: 4m x 4n, warp tile 32x32),
// cp.async 3-stage pipeline.
// ============================================================================
#define GBK    64
#define GSTR   72                    // bf16 elems per smem row (64 data + 8 pad)
#define GMATB  (128 * GSTR * 2)      // 18432 B
#define GSTAGEB (4 * GMATB)          // 73728 B
#define GEMM_SMEM (3 * GSTAGEB)      // 221184 B

__global__ __launch_bounds__(512, 1) void gemm_bf3(const __nv_bfloat16* __restrict__ Ah,
                                                   const __nv_bfloat16* __restrict__ Al,
                                                   const __nv_bfloat16* __restrict__ Bh,
                                                   const __nv_bfloat16* __restrict__ Bl,
                                                   float* __restrict__ C,
                                                   int N, int K, int nBlkN) {
    extern __shared__ char sm[];
    const uint32_t sb = smem_u32(sm);

    int lin = blockIdx.x;
    int grp = lin / (8 * nBlkN);
    int rem = lin - grp * (8 * nBlkN);
    int bm  = grp * 8 + (rem & 7);
    int bn  = rem >> 3;

    const int t = threadIdx.x, lane = t & 31, wid = t >> 5;
    const int wm = wid & 3, wn = wid >> 2;   // 4m x 4n warps, 32x32 warp tile

    const __nv_bfloat16* mats[4] = {
        Ah + (size_t)bm * 128 * K, Al + (size_t)bm * 128 * K,
        Bh + (size_t)bn * 128 * K, Bl + (size_t)bn * 128 * K };

    float acc[2][4][4];
#pragma unroll
    for (int i = 0; i < 2; i++)
#pragma unroll
        for (int j = 0; j < 4; j++)
#pragma unroll
            for (int k = 0; k < 4; k++) acc[i][j][k] = 0.0f;

    const int nchunk = K / GBK;

    auto issue = [&](int g) {
        const int s = g % 3;
        const uint32_t stg = sb + s * GSTAGEB;
        const int k0 = g * GBK;
#pragma unroll
        for (int m = 0; m < 4; m++) {
            const __nv_bfloat16* src = mats[m] + k0;
            const uint32_t dstm = stg + m * GMATB;
#pragma unroll
            for (int i = 0; i < 2; i++) {
                int id  = t + i * 512;         // 0..1023
                int row = id >> 3, c = id & 7;
                cp_async16(dstm + (uint32_t)(row * GSTR + c * 8) * 2,
                           src + (size_t)row * K + c * 8);
            }
        }
        CP_COMMIT();
    };

    auto compute = [&](int st) {
        const uint32_t base = sb + st * GSTAGEB;
        const uint32_t aOff = (uint32_t)((wm * 32 + (lane & 15)) * GSTR + (lane >> 4) * 8) * 2;
        const uint32_t bOff = (uint32_t)((wn * 32 + (lane & 15)) * GSTR + (lane >> 4) * 8) * 2;
#pragma unroll
        for (int kk = 0; kk < 4; kk++) {
            const uint32_t ko = (uint32_t)(kk * 16) * 2;
            uint32_t ahf[2][4], alf[2][4];
#pragma unroll
            for (int mt = 0; mt < 2; mt++) {
                uint32_t off = aOff + (uint32_t)(mt * 16 * GSTR) * 2 + ko;
                ldmatrix_x4(ahf[mt][0], ahf[mt][1], ahf[mt][2], ahf[mt][3], base + off);
                ldmatrix_x4(alf[mt][0], alf[mt][1], alf[mt][2], alf[mt][3], base + GMATB + off);
            }
            uint32_t bhf[2][4], blf[2][4];
#pragma unroll
            for (int g = 0; g < 2; g++) {
                uint32_t off = bOff + (uint32_t)(g * 16 * GSTR) * 2 + ko;
                ldmatrix_x4(bhf[g][0], bhf[g][1], bhf[g][2], bhf[g][3], base + 2 * GMATB + off);
                ldmatrix_x4(blf[g][0], blf[g][1], blf[g][2], blf[g][3], base + 3 * GMATB + off);
            }
#pragma unroll
            for (int mt = 0; mt < 2; mt++) {
#pragma unroll
                for (int g = 0; g < 2; g++) {
                    mma_bf16(acc[mt][2 * g],     ahf[mt], bhf[g][0], bhf[g][2]);
                    mma_bf16(acc[mt][2 * g],     ahf[mt], blf[g][0], blf[g][2]);
                    mma_bf16(acc[mt][2 * g],     alf[mt], bhf[g][0], bhf[g][2]);
                    mma_bf16(acc[mt][2 * g + 1], ahf[mt], bhf[g][1], bhf[g][3]);
                    mma_bf16(acc[mt][2 * g + 1], ahf[mt], blf[g][1], blf[g][3]);
                    mma_bf16(acc[mt][2 * g + 1], alf[mt], bhf[g][1], bhf[g][3]);
                }
            }
        }
    };

    issue(0);
    issue(1);
    for (int c = 0; c < nchunk; c++) {
        if (c >= nchunk - 2) { CP_WAIT0(); } else { CP_WAIT1(); }
        __syncthreads();
        if (c + 2 < nchunk) issue(c + 2);
        compute(c % 3);
    }

    const int rowBase = bm * 128 + wm * 32 + (lane >> 2);
    const int colBase = bn * 128 + wn * 32 + (lane & 3) * 2;
#pragma unroll
    for (int mt = 0; mt < 2; mt++) {
#pragma unroll
        for (int nt = 0; nt < 4; nt++) {
            float* c0 = C + (size_t)(rowBase + mt * 16) * N + colBase + nt * 8;
            *(float2*)c0                   = make_float2(acc[mt][nt][0], acc[mt][nt][1]);
            *(float2*)(c0 + (size_t)8 * N) = make_float2(acc[mt][nt][2], acc[mt][nt][3]);
        }
    }
}

// ============================================================================
// RoPE (fp32, in place on g_qkv)
// ============================================================================
__global__ __launch_bounds__(256) void rope_kernel(float* __restrict__ qkv,
                                                   const float* __restrict__ cosb,
                                                   const float* __restrict__ sinb) {
    int p = blockIdx.x * blockDim.x + threadIdx.x;
    int d    = p & 63;
    int rest = p >> 6;
    int hh   = rest % (NH_ + NKV_);
    int bs   = rest / (NH_ + NKV_);
    if (bs >= TOK) return;

    size_t base = (size_t)bs * OSZ;
    int off = (hh < NH_) ? (hh * HD_) : (QSZ + (hh - NH_) * HD_);

    float x1 = qkv[base + off + d];
    float x2 = qkv[base + off + d + 64];
    size_t cb = (size_t)bs * HD_;
    float c1 = cosb[cb + d],      s1 = sinb[cb + d];
    float c2 = cosb[cb + d + 64], s2 = sinb[cb + d + 64];

    qkv[base + off + d]      = x1 * c1 - x2 * s1;
    qkv[base + off + d + 64] = x2 * c2 + x1 * s2;
}

// ============================================================================
// Tensor-core flash attention (unchanged from R5 — validated).
// Q tile 128 x KV tile 64, 8 warps (16 q-rows each), bf16 hi/lo 3-pass for
// QK and PV; softmax fp32 in fragments. Output written as bf16 hi/lo.
// ============================================================================
#define ASTR 136                     // bf16 elems per smem row
#define AQB  (128 * ASTR * 2)        // 34816 B (Q matrix)
#define AKB  (64 * ASTR * 2)         // 17408 B (K/V matrix)
#define OFF_QH 0
#define OFF_QL (AQB)
#define OFF_KH (2 * AQB)
#define OFF_KL (2 * AQB + AKB)
#define OFF_VH (2 * AQB + 2 * AKB)
#define OFF_VL (2 * AQB + 3 * AKB)
#define ATTN_SMEM (2 * AQB + 4 * AKB)   // 139264 B

__global__ __launch_bounds__(256, 1) void attn_tc(const float* __restrict__ qkv,
                                                  __nv_bfloat16* __restrict__ outh,
                                                  __nv_bfloat16* __restrict__ outl) {
    extern __shared__ char sm[];
    const uint32_t sb = smem_u32(sm);

    const int qt = (int)gridDim.x - 1 - (int)blockIdx.x;
    const int bh = blockIdx.y;
    const int b  = bh >> 5;
    const int h  = bh & 31;
    const int kvh = h >> 2;

    const float* qbase = qkv + (size_t)b * S_ * OSZ + h * HD_;
    const float* kbase = qkv + (size_t)b * S_ * OSZ + QSZ + kvh * HD_;
    const float* vbase = kbase + KVSZ;

    const int t = threadIdx.x, lane = t & 31, wid = t >> 5;
    const int q0 = qt * 128;
    const int wRow = wid * 16;

#pragma unroll
    for (int i = 0; i < 16; i++) {
        int idx = t + i * 256;
        int r   = idx >> 5;
        int c4  = (idx & 31) * 4;
        float4 v = *(const float4*)(qbase + (size_t)(q0 + r) * OSZ + c4);
        v.x *= SCALING; v.y *= SCALING; v.z *= SCALING; v.w *= SCALING;
        uint32_t h01 = pack_hi(v.x, v.y), h23 = pack_hi(v.z, v.w);
        uint32_t off = (uint32_t)(r * ASTR + c4) * 2;
        *(uint2*)(sm + OFF_QH + off) = make_uint2(h01, h23);
        *(uint2*)(sm + OFF_QL + off) = make_uint2(pack_lo(v.x, v.y, h01), pack_lo(v.z, v.w, h23));
    }

    float m0 = -1e30f, m1 = -1e30f, l0 = 0.0f, l1 = 0.0f;
    float o[16][4];
#pragma unroll
    for (int i = 0; i < 16; i++)
#pragma unroll
        for (int j = 0; j < 4; j++) o[i][j] = 0.0f;

    const int nkv = qt * 2 + 2;
    for (int kt = 0; kt < nkv; kt++) {
        const int k0 = kt * 64;

        float4 stg[16];
        {
            int r  = t >> 5;
            int c4 = (t & 31) * 4;
#pragma unroll
            for (int i = 0; i < 8; i++)
                stg[i] = *(const float4*)(kbase + (size_t)(k0 + r + i * 8) * OSZ + c4);
#pragma unroll
            for (int i = 0; i < 8; i++)
                stg[8 + i] = *(const float4*)(vbase + (size_t)(k0 + r + i * 8) * OSZ + c4);
        }
        __syncthreads();
        {
            int r  = t >> 5;
            int c4 = (t & 31) * 4;
#pragma unroll
            for (int i = 0; i < 8; i++) {
                uint32_t off = (uint32_t)((r + i * 8) * ASTR + c4) * 2;
                float4 v = stg[i];
                uint32_t h01 = pack_hi(v.x, v.y), h23 = pack_hi(v.z, v.w);
                *(uint2*)(sm + OFF_KH + off) = make_uint2(h01, h23);
                *(uint2*)(sm + OFF_KL + off) = make_uint2(pack_lo(v.x, v.y, h01), pack_lo(v.z, v.w, h23));
                float4 w = stg[8 + i];
                uint32_t g01 = pack_hi(w.x, w.y), g23 = pack_hi(w.z, w.w);
                *(uint2*)(sm + OFF_VH + off) = make_uint2(g01, g23);
                *(uint2*)(sm + OFF_VL + off) = make_uint2(pack_lo(w.x, w.y, g01), pack_lo(w.z, w.w, g23));
            }
        }
        __syncthreads();

        float sacc[8][4];
#pragma unroll
        for (int i = 0; i < 8; i++)
#pragma unroll
            for (int j = 0; j < 4; j++) sacc[i][j] = 0.0f;

        const uint32_t aOff = (uint32_t)((wRow + (lane & 15)) * ASTR + (lane >> 4) * 8) * 2;
        const uint32_t bOff = (uint32_t)(((lane & 15)) * ASTR + (lane >> 4) * 8) * 2;
#pragma unroll
        for (int kk = 0; kk < 8; kk++) {
            const uint32_t ko = (uint32_t)(kk * 16) * 2;
            uint32_t qh[4], ql[4];
            ldmatrix_x4(qh[0], qh[1], qh[2], qh[3], sb + OFF_QH + aOff + ko);
            ldmatrix_x4(ql[0], ql[1], ql[2], ql[3], sb + OFF_QL + aOff + ko);
#pragma unroll
            for (int g = 0; g < 4; g++) {
                uint32_t off = bOff + (uint32_t)(g * 16 * ASTR) * 2 + ko;
                uint32_t kh[4], kl[4];
                ldmatrix_x4(kh[0], kh[1], kh[2], kh[3], sb + OFF_KH + off);
                ldmatrix_x4(kl[0], kl[1], kl[2], kl[3], sb + OFF_KL + off);
                mma_bf16(sacc[2 * g],     qh, kh[0], kh[2]);
                mma_bf16(sacc[2 * g],     qh, kl[0], kl[2]);
                mma_bf16(sacc[2 * g],     ql, kh[0], kh[2]);
                mma_bf16(sacc[2 * g + 1], qh, kh[1], kh[3]);
                mma_bf16(sacc[2 * g + 1], qh, kl[1], kl[3]);
                mma_bf16(sacc[2 * g + 1], ql, kh[1], kh[3]);
            }
        }

        const int r0 = q0 + wRow + (lane >> 2);
        const int r1 = r0 + 8;
        if (k0 + 63 > q0 + wRow) {
#pragma unroll
            for (int nt = 0; nt < 8; nt++) {
                int c = k0 + nt * 8 + (lane & 3) * 2;
                if (c     > r0) sacc[nt][0] = -1e30f;
                if (c + 1 > r0) sacc[nt][1] = -1e30f;
                if (c     > r1) sacc[nt][2] = -1e30f;
                if (c + 1 > r1) sacc[nt][3] = -1e30f;
            }
        }

        float mx0 = m0, mx1 = m1;
#pragma unroll
        for (int nt = 0; nt < 8; nt++) {
            mx0 = fmaxf(mx0, fmaxf(sacc[nt][0], sacc[nt][1]));
            mx1 = fmaxf(mx1, fmaxf(sacc[nt][2], sacc[nt][3]));
        }
        mx0 = fmaxf(mx0, __shfl_xor_sync(0xFFFFFFFFu, mx0, 1));
        mx0 = fmaxf(mx0, __shfl_xor_sync(0xFFFFFFFFu, mx0, 2));
        mx1 = fmaxf(mx1, __shfl_xor_sync(0xFFFFFFFFu, mx1, 1));
        mx1 = fmaxf(mx1, __shfl_xor_sync(0xFFFFFFFFu, mx1, 2));
        float f0 = __expf(m0 - mx0), f1 = __expf(m1 - mx1);
        float sum0 = 0.0f, sum1 = 0.0f;
#pragma unroll
        for (int nt = 0; nt < 8; nt++) {
            sacc[nt][0] = __expf(sacc[nt][0] - mx0);
            sacc[nt][1] = __expf(sacc[nt][1] - mx0);
            sacc[nt][2] = __expf(sacc[nt][2] - mx1);
            sacc[nt][3] = __expf(sacc[nt][3] - mx1);
            sum0 += sacc[nt][0] + sacc[nt][1];
            sum1 += sacc[nt][2] + sacc[nt][3];
        }
        sum0 += __shfl_xor_sync(0xFFFFFFFFu, sum0, 1);
        sum0 += __shfl_xor_sync(0xFFFFFFFFu, sum0, 2);
        sum1 += __shfl_xor_sync(0xFFFFFFFFu, sum1, 1);
        sum1 += __shfl_xor_sync(0xFFFFFFFFu, sum1, 2);
        m0 = mx0; m1 = mx1;
        l0 = l0 * f0 + sum0;
        l1 = l1 * f1 + sum1;
#pragma unroll
        for (int d = 0; d < 16; d++) {
            o[d][0] *= f0; o[d][1] *= f0; o[d][2] *= f1; o[d][3] *= f1;
        }

#pragma unroll
        for (int kt2 = 0; kt2 < 4; kt2++) {
            uint32_t Ph[4], Pl[4];
            Ph[0] = pack_hi(sacc[2 * kt2][0],     sacc[2 * kt2][1]);
            Pl[0] = pack_lo(sacc[2 * kt2][0],     sacc[2 * kt2][1],     Ph[0]);
            Ph[1] = pack_hi(sacc[2 * kt2][2],     sacc[2 * kt2][3]);
            Pl[1] = pack_lo(sacc[2 * kt2][2],     sacc[2 * kt2][3],     Ph[1]);
            Ph[2] = pack_hi(sacc[2 * kt2 + 1][0], sacc[2 * kt2 + 1][1]);
            Pl[2] = pack_lo(sacc[2 * kt2 + 1][0], sacc[2 * kt2 + 1][1], Ph[2]);
            Ph[3] = pack_hi(sacc[2 * kt2 + 1][2], sacc[2 * kt2 + 1][3]);
            Pl[3] = pack_lo(sacc[2 * kt2 + 1][2], sacc[2 * kt2 + 1][3], Ph[3]);

            const int kRow = kt2 * 16 + (lane & 7) + ((lane >> 4) & 1) * 8;
#pragma unroll
            for (int gd = 0; gd < 8; gd++) {
                const int nCol = gd * 16 + ((lane >> 3) & 1) * 8;
                const uint32_t off = (uint32_t)(kRow * ASTR + nCol) * 2;
                uint32_t vh[4], vl[4];
                ldmatrix_x4t(vh[0], vh[1], vh[2], vh[3], sb + OFF_VH + off);
                ldmatrix_x4t(vl[0], vl[1], vl[2], vl[3], sb + OFF_VL + off);
                mma_bf16(o[2 * gd],     Ph, vh[0], vh[2]);
                mma_bf16(o[2 * gd],     Ph, vl[0], vl[2]);
                mma_bf16(o[2 * gd],     Pl, vh[0], vh[2]);
                mma_bf16(o[2 * gd + 1], Ph, vh[1], vh[3]);
                mma_bf16(o[2 * gd + 1], Ph, vl[1], vl[3]);
                mma_bf16(o[2 * gd + 1], Pl, vh[1], vh[3]);
            }
        }
    }

    const float i0 = 1.0f / l0, i1 = 1.0f / l1;
    const int tok0 = b * S_ + q0 + wRow + (lane >> 2);
    const int tok1 = tok0 + 8;
    const int colB = h * HD_ + (lane & 3) * 2;
#pragma unroll
    for (int d = 0; d < 16; d++) {
        int col = colB + d * 8;
        float v0 = o[d][0] * i0, v1 = o[d][1] * i0;
        float v2 = o[d][2] * i1, v3 = o[d][3] * i1;
        uint32_t h01 = pack_hi(v0, v1);
        uint32_t h23 = pack_hi(v2, v3);
        *(uint32_t*)(outh + (size_t)tok0 * QSZ + col) = h01;
        *(uint32_t*)(outl + (size_t)tok0 * QSZ + col) = pack_lo(v0, v1, h01);
        *(uint32_t*)(outh + (size_t)tok1 * QSZ + col) = h23;
        *(uint32_t*)(outl + (size_t)tok1 * QSZ + col) = pack_lo(v2, v3, h23);
    }
}

// ============================================================================
// kernel_launch
// ============================================================================
extern "C" void kernel_launch(void* const* d_in, const int* in_sizes, int n_in,
                              void* d_out, int out_size) {
    const float* hs    = (const float*)d_in[0];
    const float* cosb  = (const float*)d_in[1];
    const float* sinb  = (const float*)d_in[2];
    const float* w_qkv = (const float*)d_in[3];
    const float* w_o   = (const float*)d_in[4];
    float* out = (float*)d_out;

    float* qkv;  cudaGetSymbolAddress((void**)&qkv, g_qkv);
    __nv_bfloat16 *hsh, *hsl, *wqh, *wql, *woh, *wol, *ath, *atl;
    cudaGetSymbolAddress((void**)&hsh, g_hsh);
    cudaGetSymbolAddress((void**)&hsl, g_hsl);
    cudaGetSymbolAddress((void**)&wqh, g_wqh);
    cudaGetSymbolAddress((void**)&wql, g_wql);
    cudaGetSymbolAddress((void**)&woh, g_woh);
    cudaGetSymbolAddress((void**)&wol, g_wol);
    cudaGetSymbolAddress((void**)&ath, g_ath);
    cudaGetSymbolAddress((void**)&atl, g_atl);

    cudaFuncSetAttribute(gemm_bf3, cudaFuncAttributeMaxDynamicSharedMemorySize, GEMM_SMEM);
    cudaFuncSetAttribute(attn_tc,  cudaFuncAttributeMaxDynamicSharedMemorySize, ATTN_SMEM);

    // 0) split fp32 operands into bf16 hi/lo
    split_kernel<<<(TOK * HID_ / 4) / 256, 256>>>(hs, hsh, hsl, TOK * HID_ / 4);
    split_kernel<<<(OSZ * HID_ / 4) / 256, 256>>>(w_qkv, wqh, wql, OSZ * HID_ / 4);
    split_kernel<<<(HID_ * QSZ / 4) / 256, 256>>>(w_o, woh, wol, HID_ * QSZ / 4);

    // 1) QKV projection
    gemm_bf3<<<(TOK / 128) * (OSZ / 128), 512, GEMM_SMEM>>>(hsh, hsl, wqh, wql, qkv,
                                                            OSZ, HID_, OSZ / 128);
    // 2) RoPE
    rope_kernel<<<TOK * (NH_ + NKV_) * 64 / 256, 256>>>(qkv, cosb, sinb);

    // 3) Attention (writes bf16 hi/lo)
    {
        dim3 grid(S_ / 128, B_ * NH_);
        attn_tc<<<grid, 256, ATTN_SMEM>>>(qkv, ath, atl);
    }

    // 4) Output projection
    gemm_bf3<<<(TOK / 128) * (HID_ / 128), 512, GEMM_SMEM>>>(ath, atl, woh, wol, out,
                                                             HID_, QSZ, HID_ / 128);
}

// round 7
// speedup vs baseline: 3.3272x; 1.2761x over previous
#include <cuda_runtime.h>
#include <cuda_bf16.h>
#include <cuda_fp16.h>
#include <cstdint>

// ===== Problem constants =====
#define B_    2
#define S_    2048
#define HID_  4096
#define NH_   32
#define NKV_  8
#define HD_   128
#define QSZ   (NH_ * HD_)
#define KVSZ  (NKV_ * HD_)
#define OSZ   (QSZ + 2 * KVSZ)     // 6144
#define TOK   (B_ * S_)            // 4096
#define SCALING 0.08838834764831843f

// ===== Scratch =====
__device__ float g_qkv[TOK * OSZ];                  // fp32 QKV (rope in place)
__device__ __half g_hsh[TOK * HID_],  g_hsl[TOK * HID_];   // hidden_states fp16 hi/lo
__device__ __half g_wq[OSZ * HID_];                        // w_qkv fp16
__device__ __half g_wo[HID_ * QSZ];                        // w_o fp16
__device__ __half g_ath[TOK * QSZ],   g_atl[TOK * QSZ];    // attention out fp16 hi/lo

// ============================================================================
// PTX helpers
// ============================================================================
__device__ __forceinline__ uint32_t smem_u32(const void* p) {
    uint32_t a;
    asm("{ .reg .u64 t; cvta.to.shared.u64 t, %1; cvt.u32.u64 %0, t; }" : "=r"(a) : "l"(p));
    return a;
}
__device__ __forceinline__ void ldmatrix_x4(uint32_t& r0, uint32_t& r1,
                                            uint32_t& r2, uint32_t& r3, uint32_t addr) {
    asm volatile("ldmatrix.sync.aligned.m8n8.x4.shared.b16 {%0,%1,%2,%3}, [%4];"
                 : "=r"(r0), "=r"(r1), "=r"(r2), "=r"(r3) : "r"(addr));
}
__device__ __forceinline__ void ldmatrix_x4t(uint32_t& r0, uint32_t& r1,
                                             uint32_t& r2, uint32_t& r3, uint32_t addr) {
    asm volatile("ldmatrix.sync.aligned.m8n8.x4.trans.shared.b16 {%0,%1,%2,%3}, [%4];"
                 : "=r"(r0), "=r"(r1), "=r"(r2), "=r"(r3) : "r"(addr));
}
__device__ __forceinline__ void mma_bf16(float* d, const uint32_t* a, uint32_t b0, uint32_t b1) {
    asm volatile(
        "mma.sync.aligned.m16n8k16.row.col.f32.bf16.bf16.f32 "
        "{%0,%1,%2,%3}, {%4,%5,%6,%7}, {%8,%9}, {%0,%1,%2,%3};"
        : "+f"(d[0]), "+f"(d[1]), "+f"(d[2]), "+f"(d[3])
        : "r"(a[0]), "r"(a[1]), "r"(a[2]), "r"(a[3]), "r"(b0), "r"(b1));
}
__device__ __forceinline__ void mma_f16(float* d, const uint32_t* a, uint32_t b0, uint32_t b1) {
    asm volatile(
        "mma.sync.aligned.m16n8k16.row.col.f32.f16.f16.f32 "
        "{%0,%1,%2,%3}, {%4,%5,%6,%7}, {%8,%9}, {%0,%1,%2,%3};"
        : "+f"(d[0]), "+f"(d[1]), "+f"(d[2]), "+f"(d[3])
        : "r"(a[0]), "r"(a[1]), "r"(a[2]), "r"(a[3]), "r"(b0), "r"(b1));
}
__device__ __forceinline__ void cp_async16(uint32_t s, const void* g) {
    asm volatile("cp.async.cg.shared.global [%0], [%1], 16;" :: "r"(s), "l"(g) : "memory");
}
#define CP_COMMIT() asm volatile("cp.async.commit_group;" ::: "memory")
#define CP_WAIT1()  asm volatile("cp.async.wait_group 1;" ::: "memory")
#define CP_WAIT0()  asm volatile("cp.async.wait_group 0;" ::: "memory")

// bf16 pack (attention internals)
__device__ __forceinline__ uint32_t pack_hi(float a, float b) {
    __nv_bfloat162 h = __floats2bfloat162_rn(a, b);
    return *(uint32_t*)&h;
}
__device__ __forceinline__ uint32_t pack_lo(float a, float b, uint32_t hi) {
    __nv_bfloat162 h = *(__nv_bfloat162*)&hi;
    __nv_bfloat162 l = __floats2bfloat162_rn(a - __bfloat162float(h.x),
                                             b - __bfloat162float(h.y));
    return *(uint32_t*)&l;
}
// fp16 pack (GEMM operands)
__device__ __forceinline__ uint32_t pack_hi_h(float a, float b) {
    __half2 h = __floats2half2_rn(a, b);
    return *(uint32_t*)&h;
}
__device__ __forceinline__ uint32_t pack_lo_h(float a, float b, uint32_t hi) {
    __half2 h = *(__half2*)&hi;
    __half2 l = __floats2half2_rn(a - __half2float(h.x), b - __half2float(h.y));
    return *(uint32_t*)&l;
}

// ============================================================================
// split kernels
// ============================================================================
__global__ __launch_bounds__(256) void split2h_kernel(const float* __restrict__ in,
                                                      __half* __restrict__ hi,
                                                      __half* __restrict__ lo, int n4) {
    int i = blockIdx.x * blockDim.x + threadIdx.x;
    if (i >= n4) return;
    float4 v = ((const float4*)in)[i];
    uint32_t h01 = pack_hi_h(v.x, v.y), h23 = pack_hi_h(v.z, v.w);
    ((uint2*)hi)[i] = make_uint2(h01, h23);
    ((uint2*)lo)[i] = make_uint2(pack_lo_h(v.x, v.y, h01), pack_lo_h(v.z, v.w, h23));
}
__global__ __launch_bounds__(256) void cvt_h_kernel(const float* __restrict__ in,
                                                    __half* __restrict__ o, int n4) {
    int i = blockIdx.x * blockDim.x + threadIdx.x;
    if (i >= n4) return;
    float4 v = ((const float4*)in)[i];
    ((uint2*)o)[i] = make_uint2(pack_hi_h(v.x, v.y), pack_hi_h(v.z, v.w));
}

// ============================================================================
// fp16 2-pass GEMM: C[M,N] = (Ah+Al)[M,K] * B[N,K]^T
// 128x128x128 tile, 512 threads (16 warps, 4m x 4n, warp tile 32x32),
// 2-stage cp.async pipeline. Smem rows: 128 data fp16 + 8 pad.
// ============================================================================
#define GBK    128
#define GSTR   136                   // fp16 elems per smem row
#define GMATB  (128 * GSTR * 2)      // 34816 B
#define GSTAGEB (3 * GMATB)          // 104448 B (Ah, Al, B)
#define GEMM_SMEM (2 * GSTAGEB)      // 208896 B

__global__ __launch_bounds__(512, 1) void gemm_h2(const __half* __restrict__ Ah,
                                                  const __half* __restrict__ Al,
                                                  const __half* __restrict__ Bw,
                                                  float* __restrict__ C,
                                                  int N, int K, int nBlkN) {
    extern __shared__ char sm[];
    const uint32_t sb = smem_u32(sm);

    int lin = blockIdx.x;
    int grp = lin / (8 * nBlkN);
    int rem = lin - grp * (8 * nBlkN);
    int bm  = grp * 8 + (rem & 7);
    int bn  = rem >> 3;

    const int t = threadIdx.x, lane = t & 31, wid = t >> 5;
    const int wm = wid & 3, wn = wid >> 2;

    const __half* mats[3] = {
        Ah + (size_t)bm * 128 * K, Al + (size_t)bm * 128 * K,
        Bw + (size_t)bn * 128 * K };

    float acc[2][4][4];
#pragma unroll
    for (int i = 0; i < 2; i++)
#pragma unroll
        for (int j = 0; j < 4; j++)
#pragma unroll
            for (int k = 0; k < 4; k++) acc[i][j][k] = 0.0f;

    const int nchunk = K / GBK;

    auto issue = [&](int g) {
        const int s = g & 1;
        const uint32_t stg = sb + s * GSTAGEB;
        const int k0 = g * GBK;
#pragma unroll
        for (int m = 0; m < 3; m++) {
            const __half* src = mats[m] + k0;
            const uint32_t dstm = stg + m * GMATB;
#pragma unroll
            for (int i = 0; i < 4; i++) {
                int id  = t + i * 512;         // 0..2047
                int row = id >> 4, c = id & 15;
                cp_async16(dstm + (uint32_t)(row * GSTR + c * 8) * 2,
                           src + (size_t)row * K + c * 8);
            }
        }
        CP_COMMIT();
    };

    auto compute = [&](int st) {
        const uint32_t base = sb + st * GSTAGEB;
        const uint32_t aOff = (uint32_t)((wm * 32 + (lane & 15)) * GSTR + (lane >> 4) * 8) * 2;
        const uint32_t bOff = (uint32_t)((wn * 32 + (lane & 15)) * GSTR + (lane >> 4) * 8) * 2;
#pragma unroll
        for (int kk = 0; kk < 8; kk++) {
            const uint32_t ko = (uint32_t)(kk * 16) * 2;
            uint32_t ahf[2][4], alf[2][4];
#pragma unroll
            for (int mt = 0; mt < 2; mt++) {
                uint32_t off = aOff + (uint32_t)(mt * 16 * GSTR) * 2 + ko;
                ldmatrix_x4(ahf[mt][0], ahf[mt][1], ahf[mt][2], ahf[mt][3], base + off);
                ldmatrix_x4(alf[mt][0], alf[mt][1], alf[mt][2], alf[mt][3], base + GMATB + off);
            }
            uint32_t bf[2][4];
#pragma unroll
            for (int g = 0; g < 2; g++) {
                uint32_t off = bOff + (uint32_t)(g * 16 * GSTR) * 2 + ko;
                ldmatrix_x4(bf[g][0], bf[g][1], bf[g][2], bf[g][3], base + 2 * GMATB + off);
            }
#pragma unroll
            for (int mt = 0; mt < 2; mt++) {
#pragma unroll
                for (int g = 0; g < 2; g++) {
                    mma_f16(acc[mt][2 * g],     ahf[mt], bf[g][0], bf[g][2]);
                    mma_f16(acc[mt][2 * g],     alf[mt], bf[g][0], bf[g][2]);
                    mma_f16(acc[mt][2 * g + 1], ahf[mt], bf[g][1], bf[g][3]);
                    mma_f16(acc[mt][2 * g + 1], alf[mt], bf[g][1], bf[g][3]);
                }
            }
        }
    };

    issue(0);
    issue(1);
    for (int c = 0; c < nchunk; c++) {
        if (c >= nchunk - 1) { CP_WAIT0(); } else { CP_WAIT1(); }
        __syncthreads();
        compute(c & 1);
        __syncthreads();
        if (c + 2 < nchunk) issue(c + 2);
    }

    const int rowBase = bm * 128 + wm * 32 + (lane >> 2);
    const int colBase = bn * 128 + wn * 32 + (lane & 3) * 2;
#pragma unroll
    for (int mt = 0; mt < 2; mt++) {
#pragma unroll
        for (int nt = 0; nt < 4; nt++) {
            float* c0 = C + (size_t)(rowBase + mt * 16) * N + colBase + nt * 8;
            *(float2*)c0                   = make_float2(acc[mt][nt][0], acc[mt][nt][1]);
            *(float2*)(c0 + (size_t)8 * N) = make_float2(acc[mt][nt][2], acc[mt][nt][3]);
        }
    }
}

// ============================================================================
// RoPE (fp32, in place on g_qkv)
// ============================================================================
__global__ __launch_bounds__(256) void rope_kernel(float* __restrict__ qkv,
                                                   const float* __restrict__ cosb,
                                                   const float* __restrict__ sinb) {
    int p = blockIdx.x * blockDim.x + threadIdx.x;
    int d    = p & 63;
    int rest = p >> 6;
    int hh   = rest % (NH_ + NKV_);
    int bs   = rest / (NH_ + NKV_);
    if (bs >= TOK) return;

    size_t base = (size_t)bs * OSZ;
    int off = (hh < NH_) ? (hh * HD_) : (QSZ + (hh - NH_) * HD_);

    float x1 = qkv[base + off + d];
    float x2 = qkv[base + off + d + 64];
    size_t cb = (size_t)bs * HD_;
    float c1 = cosb[cb + d],      s1 = sinb[cb + d];
    float c2 = cosb[cb + d + 64], s2 = sinb[cb + d + 64];

    qkv[base + off + d]      = x1 * c1 - x2 * s1;
    qkv[base + off + d + 64] = x2 * c2 + x1 * s2;
}

// ============================================================================
// Tensor-core flash attention (bf16 3-pass internals — validated).
// Epilogue now writes fp16 hi/lo for GEMM2's A operand.
// ============================================================================
#define ASTR 136
#define AQB  (128 * ASTR * 2)
#define AKB  (64 * ASTR * 2)
#define OFF_QH 0
#define OFF_QL (AQB)
#define OFF_KH (2 * AQB)
#define OFF_KL (2 * AQB + AKB)
#define OFF_VH (2 * AQB + 2 * AKB)
#define OFF_VL (2 * AQB + 3 * AKB)
#define ATTN_SMEM (2 * AQB + 4 * AKB)

__global__ __launch_bounds__(256, 1) void attn_tc(const float* __restrict__ qkv,
                                                  __half* __restrict__ outh,
                                                  __half* __restrict__ outl) {
    extern __shared__ char sm[];
    const uint32_t sb = smem_u32(sm);

    const int qt = (int)gridDim.x - 1 - (int)blockIdx.x;
    const int bh = blockIdx.y;
    const int b  = bh >> 5;
    const int h  = bh & 31;
    const int kvh = h >> 2;

    const float* qbase = qkv + (size_t)b * S_ * OSZ + h * HD_;
    const float* kbase = qkv + (size_t)b * S_ * OSZ + QSZ + kvh * HD_;
    const float* vbase = kbase + KVSZ;

    const int t = threadIdx.x, lane = t & 31, wid = t >> 5;
    const int q0 = qt * 128;
    const int wRow = wid * 16;

#pragma unroll
    for (int i = 0; i < 16; i++) {
        int idx = t + i * 256;
        int r   = idx >> 5;
        int c4  = (idx & 31) * 4;
        float4 v = *(const float4*)(qbase + (size_t)(q0 + r) * OSZ + c4);
        v.x *= SCALING; v.y *= SCALING; v.z *= SCALING; v.w *= SCALING;
        uint32_t h01 = pack_hi(v.x, v.y), h23 = pack_hi(v.z, v.w);
        uint32_t off = (uint32_t)(r * ASTR + c4) * 2;
        *(uint2*)(sm + OFF_QH + off) = make_uint2(h01, h23);
        *(uint2*)(sm + OFF_QL + off) = make_uint2(pack_lo(v.x, v.y, h01), pack_lo(v.z, v.w, h23));
    }

    float m0 = -1e30f, m1 = -1e30f, l0 = 0.0f, l1 = 0.0f;
    float o[16][4];
#pragma unroll
    for (int i = 0; i < 16; i++)
#pragma unroll
        for (int j = 0; j < 4; j++) o[i][j] = 0.0f;

    const int nkv = qt * 2 + 2;
    for (int kt = 0; kt < nkv; kt++) {
        const int k0 = kt * 64;

        float4 stg[16];
        {
            int r  = t >> 5;
            int c4 = (t & 31) * 4;
#pragma unroll
            for (int i = 0; i < 8; i++)
                stg[i] = *(const float4*)(kbase + (size_t)(k0 + r + i * 8) * OSZ + c4);
#pragma unroll
            for (int i = 0; i < 8; i++)
                stg[8 + i] = *(const float4*)(vbase + (size_t)(k0 + r + i * 8) * OSZ + c4);
        }
        __syncthreads();
        {
            int r  = t >> 5;
            int c4 = (t & 31) * 4;
#pragma unroll
            for (int i = 0; i < 8; i++) {
                uint32_t off = (uint32_t)((r + i * 8) * ASTR + c4) * 2;
                float4 v = stg[i];
                uint32_t h01 = pack_hi(v.x, v.y), h23 = pack_hi(v.z, v.w);
                *(uint2*)(sm + OFF_KH + off) = make_uint2(h01, h23);
                *(uint2*)(sm + OFF_KL + off) = make_uint2(pack_lo(v.x, v.y, h01), pack_lo(v.z, v.w, h23));
                float4 w = stg[8 + i];
                uint32_t g01 = pack_hi(w.x, w.y), g23 = pack_hi(w.z, w.w);
                *(uint2*)(sm + OFF_VH + off) = make_uint2(g01, g23);
                *(uint2*)(sm + OFF_VL + off) = make_uint2(pack_lo(w.x, w.y, g01), pack_lo(w.z, w.w, g23));
            }
        }
        __syncthreads();

        float sacc[8][4];
#pragma unroll
        for (int i = 0; i < 8; i++)
#pragma unroll
            for (int j = 0; j < 4; j++) sacc[i][j] = 0.0f;

        const uint32_t aOff = (uint32_t)((wRow + (lane & 15)) * ASTR + (lane >> 4) * 8) * 2;
        const uint32_t bOff = (uint32_t)(((lane & 15)) * ASTR + (lane >> 4) * 8) * 2;
#pragma unroll
        for (int kk = 0; kk < 8; kk++) {
            const uint32_t ko = (uint32_t)(kk * 16) * 2;
            uint32_t qh[4], ql[4];
            ldmatrix_x4(qh[0], qh[1], qh[2], qh[3], sb + OFF_QH + aOff + ko);
            ldmatrix_x4(ql[0], ql[1], ql[2], ql[3], sb + OFF_QL + aOff + ko);
#pragma unroll
            for (int g = 0; g < 4; g++) {
                uint32_t off = bOff + (uint32_t)(g * 16 * ASTR) * 2 + ko;
                uint32_t kh[4], kl[4];
                ldmatrix_x4(kh[0], kh[1], kh[2], kh[3], sb + OFF_KH + off);
                ldmatrix_x4(kl[0], kl[1], kl[2], kl[3], sb + OFF_KL + off);
                mma_bf16(sacc[2 * g],     qh, kh[0], kh[2]);
                mma_bf16(sacc[2 * g],     qh, kl[0], kl[2]);
                mma_bf16(sacc[2 * g],     ql, kh[0], kh[2]);
                mma_bf16(sacc[2 * g + 1], qh, kh[1], kh[3]);
                mma_bf16(sacc[2 * g + 1], qh, kl[1], kl[3]);
                mma_bf16(sacc[2 * g + 1], ql, kh[1], kh[3]);
            }
        }

        const int r0 = q0 + wRow + (lane >> 2);
        const int r1 = r0 + 8;
        if (k0 + 63 > q0 + wRow) {
#pragma unroll
            for (int nt = 0; nt < 8; nt++) {
                int c = k0 + nt * 8 + (lane & 3) * 2;
                if (c     > r0) sacc[nt][0] = -1e30f;
                if (c + 1 > r0) sacc[nt][1] = -1e30f;
                if (c     > r1) sacc[nt][2] = -1e30f;
                if (c + 1 > r1) sacc[nt][3] = -1e30f;
            }
        }

        float mx0 = m0, mx1 = m1;
#pragma unroll
        for (int nt = 0; nt < 8; nt++) {
            mx0 = fmaxf(mx0, fmaxf(sacc[nt][0], sacc[nt][1]));
            mx1 = fmaxf(mx1, fmaxf(sacc[nt][2], sacc[nt][3]));
        }
        mx0 = fmaxf(mx0, __shfl_xor_sync(0xFFFFFFFFu, mx0, 1));
        mx0 = fmaxf(mx0, __shfl_xor_sync(0xFFFFFFFFu, mx0, 2));
        mx1 = fmaxf(mx1, __shfl_xor_sync(0xFFFFFFFFu, mx1, 1));
        mx1 = fmaxf(mx1, __shfl_xor_sync(0xFFFFFFFFu, mx1, 2));
        float f0 = __expf(m0 - mx0), f1 = __expf(m1 - mx1);
        float sum0 = 0.0f, sum1 = 0.0f;
#pragma unroll
        for (int nt = 0; nt < 8; nt++) {
            sacc[nt][0] = __expf(sacc[nt][0] - mx0);
            sacc[nt][1] = __expf(sacc[nt][1] - mx0);
            sacc[nt][2] = __expf(sacc[nt][2] - mx1);
            sacc[nt][3] = __expf(sacc[nt][3] - mx1);
            sum0 += sacc[nt][0] + sacc[nt][1];
            sum1 += sacc[nt][2] + sacc[nt][3];
        }
        sum0 += __shfl_xor_sync(0xFFFFFFFFu, sum0, 1);
        sum0 += __shfl_xor_sync(0xFFFFFFFFu, sum0, 2);
        sum1 += __shfl_xor_sync(0xFFFFFFFFu, sum1, 1);
        sum1 += __shfl_xor_sync(0xFFFFFFFFu, sum1, 2);
        m0 = mx0; m1 = mx1;
        l0 = l0 * f0 + sum0;
        l1 = l1 * f1 + sum1;
#pragma unroll
        for (int d = 0; d < 16; d++) {
            o[d][0] *= f0; o[d][1] *= f0; o[d][2] *= f1; o[d][3] *= f1;
        }

#pragma unroll
        for (int kt2 = 0; kt2 < 4; kt2++) {
            uint32_t Ph[4], Pl[4];
            Ph[0] = pack_hi(sacc[2 * kt2][0],     sacc[2 * kt2][1]);
            Pl[0] = pack_lo(sacc[2 * kt2][0],     sacc[2 * kt2][1],     Ph[0]);
            Ph[1] = pack_hi(sacc[2 * kt2][2],     sacc[2 * kt2][3]);
            Pl[1] = pack_lo(sacc[2 * kt2][2],     sacc[2 * kt2][3],     Ph[1]);
            Ph[2] = pack_hi(sacc[2 * kt2 + 1][0], sacc[2 * kt2 + 1][1]);
            Pl[2] = pack_lo(sacc[2 * kt2 + 1][0], sacc[2 * kt2 + 1][1], Ph[2]);
            Ph[3] = pack_hi(sacc[2 * kt2 + 1][2], sacc[2 * kt2 + 1][3]);
            Pl[3] = pack_lo(sacc[2 * kt2 + 1][2], sacc[2 * kt2 + 1][3], Ph[3]);

            const int kRow = kt2 * 16 + (lane & 7) + ((lane >> 4) & 1) * 8;
#pragma unroll
            for (int gd = 0; gd < 8; gd++) {
                const int nCol = gd * 16 + ((lane >> 3) & 1) * 8;
                const uint32_t off = (uint32_t)(kRow * ASTR + nCol) * 2;
                uint32_t vh[4], vl[4];
                ldmatrix_x4t(vh[0], vh[1], vh[2], vh[3], sb + OFF_VH + off);
                ldmatrix_x4t(vl[0], vl[1], vl[2], vl[3], sb + OFF_VL + off);
                mma_bf16(o[2 * gd],     Ph, vh[0], vh[2]);
                mma_bf16(o[2 * gd],     Ph, vl[0], vl[2]);
                mma_bf16(o[2 * gd],     Pl, vh[0], vh[2]);
                mma_bf16(o[2 * gd + 1], Ph, vh[1], vh[3]);
                mma_bf16(o[2 * gd + 1], Ph, vl[1], vl[3]);
                mma_bf16(o[2 * gd + 1], Pl, vh[1], vh[3]);
            }
        }
    }

    const float i0 = 1.0f / l0, i1 = 1.0f / l1;
    const int tok0 = b * S_ + q0 + wRow + (lane >> 2);
    const int tok1 = tok0 + 8;
    const int colB = h * HD_ + (lane & 3) * 2;
#pragma unroll
    for (int d = 0; d < 16; d++) {
        int col = colB + d * 8;
        float v0 = o[d][0] * i0, v1 = o[d][1] * i0;
        float v2 = o[d][2] * i1, v3 = o[d][3] * i1;
        uint32_t h01 = pack_hi_h(v0, v1);
        uint32_t h23 = pack_hi_h(v2, v3);
        *(uint32_t*)(outh + (size_t)tok0 * QSZ + col) = h01;
        *(uint32_t*)(outl + (size_t)tok0 * QSZ + col) = pack_lo_h(v0, v1, h01);
        *(uint32_t*)(outh + (size_t)tok1 * QSZ + col) = h23;
        *(uint32_t*)(outl + (size_t)tok1 * QSZ + col) = pack_lo_h(v2, v3, h23);
    }
}

// ============================================================================
// kernel_launch
// ============================================================================
extern "C" void kernel_launch(void* const* d_in, const int* in_sizes, int n_in,
                              void* d_out, int out_size) {
    const float* hs    = (const float*)d_in[0];
    const float* cosb  = (const float*)d_in[1];
    const float* sinb  = (const float*)d_in[2];
    const float* w_qkv = (const float*)d_in[3];
    const float* w_o   = (const float*)d_in[4];
    float* out = (float*)d_out;

    float* qkv;  cudaGetSymbolAddress((void**)&qkv, g_qkv);
    __half *hsh, *hsl, *wq, *wo, *ath, *atl;
    cudaGetSymbolAddress((void**)&hsh, g_hsh);
    cudaGetSymbolAddress((void**)&hsl, g_hsl);
    cudaGetSymbolAddress((void**)&wq,  g_wq);
    cudaGetSymbolAddress((void**)&wo,  g_wo);
    cudaGetSymbolAddress((void**)&ath, g_ath);
    cudaGetSymbolAddress((void**)&atl, g_atl);

    cudaFuncSetAttribute(gemm_h2, cudaFuncAttributeMaxDynamicSharedMemorySize, GEMM_SMEM);
    cudaFuncSetAttribute(attn_tc, cudaFuncAttributeMaxDynamicSharedMemorySize, ATTN_SMEM);

    // 0) operand conversion
    split2h_kernel<<<(TOK * HID_ / 4) / 256, 256>>>(hs, hsh, hsl, TOK * HID_ / 4);
    cvt_h_kernel<<<(OSZ * HID_ / 4) / 256, 256>>>(w_qkv, wq, OSZ * HID_ / 4);
    cvt_h_kernel<<<(HID_ * QSZ / 4) / 256, 256>>>(w_o, wo, HID_ * QSZ / 4);

    // 1) QKV projection
    gemm_h2<<<(TOK / 128) * (OSZ / 128), 512, GEMM_SMEM>>>(hsh, hsl, wq, qkv,
                                                           OSZ, HID_, OSZ / 128);
    // 2) RoPE
    rope_kernel<<<TOK * (NH_ + NKV_) * 64 / 256, 256>>>(qkv, cosb, sinb);

    // 3) Attention (writes fp16 hi/lo)
    {
        dim3 grid(S_ / 128, B_ * NH_);
        attn_tc<<<grid, 256, ATTN_SMEM>>>(qkv, ath, atl);
    }

    // 4) Output projection
    gemm_h2<<<(TOK / 128) * (HID_ / 128), 512, GEMM_SMEM>>>(ath, atl, wo, out,
                                                            HID_, QSZ, HID_ / 128);
}

// round 8
// speedup vs baseline: 3.7205x; 1.1182x over previous
#include <cuda_runtime.h>
#include <cuda_bf16.h>
#include <cuda_fp16.h>
#include <cstdint>

// ===== Problem constants =====
#define B_    2
#define S_    2048
#define HID_  4096
#define NH_   32
#define NKV_  8
#define HD_   128
#define QSZ   (NH_ * HD_)
#define KVSZ  (NKV_ * HD_)
#define OSZ   (QSZ + 2 * KVSZ)     // 6144
#define TOK   (B_ * S_)            // 4096
#define SCALING 0.08838834764831843f

// ===== Scratch =====
__device__ float g_qkv[TOK * OSZ];
__device__ __half g_hsh[TOK * HID_],  g_hsl[TOK * HID_];
__device__ __half g_wq[OSZ * HID_];
__device__ __half g_wo[HID_ * QSZ];
__device__ __half g_ath[TOK * QSZ],   g_atl[TOK * QSZ];

// ============================================================================
// PTX helpers
// ============================================================================
__device__ __forceinline__ uint32_t smem_u32(const void* p) {
    uint32_t a;
    asm("{ .reg .u64 t; cvta.to.shared.u64 t, %1; cvt.u32.u64 %0, t; }" : "=r"(a) : "l"(p));
    return a;
}
__device__ __forceinline__ void ldmatrix_x4(uint32_t& r0, uint32_t& r1,
                                            uint32_t& r2, uint32_t& r3, uint32_t addr) {
    asm volatile("ldmatrix.sync.aligned.m8n8.x4.shared.b16 {%0,%1,%2,%3}, [%4];"
                 : "=r"(r0), "=r"(r1), "=r"(r2), "=r"(r3) : "r"(addr));
}
__device__ __forceinline__ void ldmatrix_x4t(uint32_t& r0, uint32_t& r1,
                                             uint32_t& r2, uint32_t& r3, uint32_t addr) {
    asm volatile("ldmatrix.sync.aligned.m8n8.x4.trans.shared.b16 {%0,%1,%2,%3}, [%4];"
                 : "=r"(r0), "=r"(r1), "=r"(r2), "=r"(r3) : "r"(addr));
}
__device__ __forceinline__ void mma_f16(float* d, const uint32_t* a, uint32_t b0, uint32_t b1) {
    asm volatile(
        "mma.sync.aligned.m16n8k16.row.col.f32.f16.f16.f32 "
        "{%0,%1,%2,%3}, {%4,%5,%6,%7}, {%8,%9}, {%0,%1,%2,%3};"
        : "+f"(d[0]), "+f"(d[1]), "+f"(d[2]), "+f"(d[3])
        : "r"(a[0]), "r"(a[1]), "r"(a[2]), "r"(a[3]), "r"(b0), "r"(b1));
}
__device__ __forceinline__ void cp_async16(uint32_t s, const void* g) {
    asm volatile("cp.async.cg.shared.global [%0], [%1], 16;" :: "r"(s), "l"(g) : "memory");
}
#define CP_COMMIT() asm volatile("cp.async.commit_group;" ::: "memory")
#define CP_WAIT2()  asm volatile("cp.async.wait_group 2;" ::: "memory")
#define CP_WAIT1()  asm volatile("cp.async.wait_group 1;" ::: "memory")
#define CP_WAIT0()  asm volatile("cp.async.wait_group 0;" ::: "memory")

__device__ __forceinline__ uint32_t pack_hi_h(float a, float b) {
    __half2 h = __floats2half2_rn(a, b);
    return *(uint32_t*)&h;
}
__device__ __forceinline__ uint32_t pack_lo_h(float a, float b, uint32_t hi) {
    __half2 h = *(__half2*)&hi;
    __half2 l = __floats2half2_rn(a - __half2float(h.x), b - __half2float(h.y));
    return *(uint32_t*)&l;
}

// ============================================================================
// split / convert kernels
// ============================================================================
__global__ __launch_bounds__(256) void split2h_kernel(const float* __restrict__ in,
                                                      __half* __restrict__ hi,
                                                      __half* __restrict__ lo, int n4) {
    int i = blockIdx.x * blockDim.x + threadIdx.x;
    if (i >= n4) return;
    float4 v = ((const float4*)in)[i];
    uint32_t h01 = pack_hi_h(v.x, v.y), h23 = pack_hi_h(v.z, v.w);
    ((uint2*)hi)[i] = make_uint2(h01, h23);
    ((uint2*)lo)[i] = make_uint2(pack_lo_h(v.x, v.y, h01), pack_lo_h(v.z, v.w, h23));
}
__global__ __launch_bounds__(256) void cvt_h_kernel(const float* __restrict__ in,
                                                    __half* __restrict__ o, int n4) {
    int i = blockIdx.x * blockDim.x + threadIdx.x;
    if (i >= n4) return;
    float4 v = ((const float4*)in)[i];
    ((uint2*)o)[i] = make_uint2(pack_hi_h(v.x, v.y), pack_hi_h(v.z, v.w));
}

// ============================================================================
// fp16 2-pass GEMM: C[M,N] = (Ah+Al)[M,K] * B[N,K]^T
// 128x128x64 tile, 512 threads (16 warps, 4m x 4n), 4-stage cp.async pipeline,
// ONE __syncthreads per chunk, 3-deep prefetch.
// ============================================================================
#define GBK    64
#define GSTR   72                    // fp16 elems per smem row (64 data + 8 pad)
#define GMATB  (128 * GSTR * 2)      // 18432 B
#define GSTAGEB (3 * GMATB)          // 55296 B (Ah, Al, B)
#define GEMM_SMEM (4 * GSTAGEB)      // 221184 B

__global__ __launch_bounds__(512, 1) void gemm_h2(const __half* __restrict__ Ah,
                                                  const __half* __restrict__ Al,
                                                  const __half* __restrict__ Bw,
                                                  float* __restrict__ C,
                                                  int N, int K, int nBlkN) {
    extern __shared__ char sm[];
    const uint32_t sb = smem_u32(sm);

    int lin = blockIdx.x;
    int grp = lin / (8 * nBlkN);
    int rem = lin - grp * (8 * nBlkN);
    int bm  = grp * 8 + (rem & 7);
    int bn  = rem >> 3;

    const int t = threadIdx.x, lane = t & 31, wid = t >> 5;
    const int wm = wid & 3, wn = wid >> 2;

    const __half* mats[3] = {
        Ah + (size_t)bm * 128 * K, Al + (size_t)bm * 128 * K,
        Bw + (size_t)bn * 128 * K };

    float acc[2][4][4];
#pragma unroll
    for (int i = 0; i < 2; i++)
#pragma unroll
        for (int j = 0; j < 4; j++)
#pragma unroll
            for (int k = 0; k < 4; k++) acc[i][j][k] = 0.0f;

    const int nchunk = K / GBK;

    auto issue = [&](int g) {
        const int s = g & 3;
        const uint32_t stg = sb + s * GSTAGEB;
        const int k0 = g * GBK;
#pragma unroll
        for (int m = 0; m < 3; m++) {
            const __half* src = mats[m] + k0;
            const uint32_t dstm = stg + m * GMATB;
#pragma unroll
            for (int i = 0; i < 2; i++) {
                int id  = t + i * 512;         // 0..1023
                int row = id >> 3, c = id & 7;
                cp_async16(dstm + (uint32_t)(row * GSTR + c * 8) * 2,
                           src + (size_t)row * K + c * 8);
            }
        }
        CP_COMMIT();
    };

    auto compute = [&](int st) {
        const uint32_t base = sb + st * GSTAGEB;
        const uint32_t aOff = (uint32_t)((wm * 32 + (lane & 15)) * GSTR + (lane >> 4) * 8) * 2;
        const uint32_t bOff = (uint32_t)((wn * 32 + (lane & 15)) * GSTR + (lane >> 4) * 8) * 2;
#pragma unroll
        for (int kk = 0; kk < 4; kk++) {
            const uint32_t ko = (uint32_t)(kk * 16) * 2;
            uint32_t ahf[2][4], alf[2][4];
#pragma unroll
            for (int mt = 0; mt < 2; mt++) {
                uint32_t off = aOff + (uint32_t)(mt * 16 * GSTR) * 2 + ko;
                ldmatrix_x4(ahf[mt][0], ahf[mt][1], ahf[mt][2], ahf[mt][3], base + off);
                ldmatrix_x4(alf[mt][0], alf[mt][1], alf[mt][2], alf[mt][3], base + GMATB + off);
            }
            uint32_t bf[2][4];
#pragma unroll
            for (int g = 0; g < 2; g++) {
                uint32_t off = bOff + (uint32_t)(g * 16 * GSTR) * 2 + ko;
                ldmatrix_x4(bf[g][0], bf[g][1], bf[g][2], bf[g][3], base + 2 * GMATB + off);
            }
#pragma unroll
            for (int mt = 0; mt < 2; mt++) {
#pragma unroll
                for (int g = 0; g < 2; g++) {
                    mma_f16(acc[mt][2 * g],     ahf[mt], bf[g][0], bf[g][2]);
                    mma_f16(acc[mt][2 * g],     alf[mt], bf[g][0], bf[g][2]);
                    mma_f16(acc[mt][2 * g + 1], ahf[mt], bf[g][1], bf[g][3]);
                    mma_f16(acc[mt][2 * g + 1], alf[mt], bf[g][1], bf[g][3]);
                }
            }
        }
    };

    issue(0); issue(1); issue(2);
    for (int c = 0; c < nchunk; c++) {
        // ensure chunk c has landed
        if (c + 3 <= nchunk) { CP_WAIT2(); }
        else if (c + 2 == nchunk) { CP_WAIT1(); }
        else { CP_WAIT0(); }
        __syncthreads();
        if (c + 3 < nchunk) issue(c + 3);   // writes stage (c-1)&3, already consumed
        compute(c & 3);
    }

    const int rowBase = bm * 128 + wm * 32 + (lane >> 2);
    const int colBase = bn * 128 + wn * 32 + (lane & 3) * 2;
#pragma unroll
    for (int mt = 0; mt < 2; mt++) {
#pragma unroll
        for (int nt = 0; nt < 4; nt++) {
            float* c0 = C + (size_t)(rowBase + mt * 16) * N + colBase + nt * 8;
            *(float2*)c0                   = make_float2(acc[mt][nt][0], acc[mt][nt][1]);
            *(float2*)(c0 + (size_t)8 * N) = make_float2(acc[mt][nt][2], acc[mt][nt][3]);
        }
    }
}

// ============================================================================
// RoPE (fp32, in place on g_qkv)
// ============================================================================
__global__ __launch_bounds__(256) void rope_kernel(float* __restrict__ qkv,
                                                   const float* __restrict__ cosb,
                                                   const float* __restrict__ sinb) {
    int p = blockIdx.x * blockDim.x + threadIdx.x;
    int d    = p & 63;
    int rest = p >> 6;
    int hh   = rest % (NH_ + NKV_);
    int bs   = rest / (NH_ + NKV_);
    if (bs >= TOK) return;

    size_t base = (size_t)bs * OSZ;
    int off = (hh < NH_) ? (hh * HD_) : (QSZ + (hh - NH_) * HD_);

    float x1 = qkv[base + off + d];
    float x2 = qkv[base + off + d + 64];
    size_t cb = (size_t)bs * HD_;
    float c1 = cosb[cb + d],      s1 = sinb[cb + d];
    float c2 = cosb[cb + d + 64], s2 = sinb[cb + d + 64];

    qkv[base + off + d]      = x1 * c1 - x2 * s1;
    qkv[base + off + d + 64] = x2 * c2 + x1 * s2;
}

// ============================================================================
// Tensor-core flash attention, fp16 2-pass.
// Q = fp16 hi/lo, K = fp16 single (QK 2 passes);
// P = fp16 hi/lo (registers), V = fp16 single (PV 2 passes).
// Output fp16 hi/lo for GEMM2.
// ============================================================================
#define ASTR 136
#define AQB  (128 * ASTR * 2)        // 34816 B
#define AKB  (64 * ASTR * 2)         // 17408 B
#define OFF_QH 0
#define OFF_QL (AQB)
#define OFF_K  (2 * AQB)
#define OFF_V  (2 * AQB + AKB)
#define ATTN_SMEM (2 * AQB + 2 * AKB)   // 104448 B

__global__ __launch_bounds__(256, 1) void attn_tc(const float* __restrict__ qkv,
                                                  __half* __restrict__ outh,
                                                  __half* __restrict__ outl) {
    extern __shared__ char sm[];
    const uint32_t sb = smem_u32(sm);

    const int qt = (int)gridDim.x - 1 - (int)blockIdx.x;
    const int bh = blockIdx.y;
    const int b  = bh >> 5;
    const int h  = bh & 31;
    const int kvh = h >> 2;

    const float* qbase = qkv + (size_t)b * S_ * OSZ + h * HD_;
    const float* kbase = qkv + (size_t)b * S_ * OSZ + QSZ + kvh * HD_;
    const float* vbase = kbase + KVSZ;

    const int t = threadIdx.x, lane = t & 31, wid = t >> 5;
    const int q0 = qt * 128;
    const int wRow = wid * 16;

    // ---- load Q tile, fold scaling, split fp16 hi/lo ----
#pragma unroll
    for (int i = 0; i < 16; i++) {
        int idx = t + i * 256;
        int r   = idx >> 5;
        int c4  = (idx & 31) * 4;
        float4 v = *(const float4*)(qbase + (size_t)(q0 + r) * OSZ + c4);
        v.x *= SCALING; v.y *= SCALING; v.z *= SCALING; v.w *= SCALING;
        uint32_t h01 = pack_hi_h(v.x, v.y), h23 = pack_hi_h(v.z, v.w);
        uint32_t off = (uint32_t)(r * ASTR + c4) * 2;
        *(uint2*)(sm + OFF_QH + off) = make_uint2(h01, h23);
        *(uint2*)(sm + OFF_QL + off) = make_uint2(pack_lo_h(v.x, v.y, h01), pack_lo_h(v.z, v.w, h23));
    }

    float m0 = -1e30f, m1 = -1e30f, l0 = 0.0f, l1 = 0.0f;
    float o[16][4];
#pragma unroll
    for (int i = 0; i < 16; i++)
#pragma unroll
        for (int j = 0; j < 4; j++) o[i][j] = 0.0f;

    const int nkv = qt * 2 + 2;
    for (int kt = 0; kt < nkv; kt++) {
        const int k0 = kt * 64;

        // stage K,V fp32 -> registers
        float4 stg[16];
        {
            int r  = t >> 5;
            int c4 = (t & 31) * 4;
#pragma unroll
            for (int i = 0; i < 8; i++)
                stg[i] = *(const float4*)(kbase + (size_t)(k0 + r + i * 8) * OSZ + c4);
#pragma unroll
            for (int i = 0; i < 8; i++)
                stg[8 + i] = *(const float4*)(vbase + (size_t)(k0 + r + i * 8) * OSZ + c4);
        }
        __syncthreads();
        {
            int r  = t >> 5;
            int c4 = (t & 31) * 4;
#pragma unroll
            for (int i = 0; i < 8; i++) {
                uint32_t off = (uint32_t)((r + i * 8) * ASTR + c4) * 2;
                float4 v = stg[i];
                *(uint2*)(sm + OFF_K + off) = make_uint2(pack_hi_h(v.x, v.y), pack_hi_h(v.z, v.w));
                float4 w = stg[8 + i];
                *(uint2*)(sm + OFF_V + off) = make_uint2(pack_hi_h(w.x, w.y), pack_hi_h(w.z, w.w));
            }
        }
        __syncthreads();

        // ---- S = Q K^T, 2-pass fp16 ----
        float sacc[8][4];
#pragma unroll
        for (int i = 0; i < 8; i++)
#pragma unroll
            for (int j = 0; j < 4; j++) sacc[i][j] = 0.0f;

        const uint32_t aOff = (uint32_t)((wRow + (lane & 15)) * ASTR + (lane >> 4) * 8) * 2;
        const uint32_t bOff = (uint32_t)(((lane & 15)) * ASTR + (lane >> 4) * 8) * 2;
#pragma unroll
        for (int kk = 0; kk < 8; kk++) {
            const uint32_t ko = (uint32_t)(kk * 16) * 2;
            uint32_t qh[4], ql[4];
            ldmatrix_x4(qh[0], qh[1], qh[2], qh[3], sb + OFF_QH + aOff + ko);
            ldmatrix_x4(ql[0], ql[1], ql[2], ql[3], sb + OFF_QL + aOff + ko);
#pragma unroll
            for (int g = 0; g < 4; g++) {
                uint32_t off = bOff + (uint32_t)(g * 16 * ASTR) * 2 + ko;
                uint32_t kh[4];
                ldmatrix_x4(kh[0], kh[1], kh[2], kh[3], sb + OFF_K + off);
                mma_f16(sacc[2 * g],     qh, kh[0], kh[2]);
                mma_f16(sacc[2 * g],     ql, kh[0], kh[2]);
                mma_f16(sacc[2 * g + 1], qh, kh[1], kh[3]);
                mma_f16(sacc[2 * g + 1], ql, kh[1], kh[3]);
            }
        }

        // ---- causal mask ----
        const int r0 = q0 + wRow + (lane >> 2);
        const int r1 = r0 + 8;
        if (k0 + 63 > q0 + wRow) {
#pragma unroll
            for (int nt = 0; nt < 8; nt++) {
                int c = k0 + nt * 8 + (lane & 3) * 2;
                if (c     > r0) sacc[nt][0] = -1e30f;
                if (c + 1 > r0) sacc[nt][1] = -1e30f;
                if (c     > r1) sacc[nt][2] = -1e30f;
                if (c + 1 > r1) sacc[nt][3] = -1e30f;
            }
        }

        // ---- online softmax ----
        float mx0 = m0, mx1 = m1;
#pragma unroll
        for (int nt = 0; nt < 8; nt++) {
            mx0 = fmaxf(mx0, fmaxf(sacc[nt][0], sacc[nt][1]));
            mx1 = fmaxf(mx1, fmaxf(sacc[nt][2], sacc[nt][3]));
        }
        mx0 = fmaxf(mx0, __shfl_xor_sync(0xFFFFFFFFu, mx0, 1));
        mx0 = fmaxf(mx0, __shfl_xor_sync(0xFFFFFFFFu, mx0, 2));
        mx1 = fmaxf(mx1, __shfl_xor_sync(0xFFFFFFFFu, mx1, 1));
        mx1 = fmaxf(mx1, __shfl_xor_sync(0xFFFFFFFFu, mx1, 2));
        float f0 = __expf(m0 - mx0), f1 = __expf(m1 - mx1);
        float sum0 = 0.0f, sum1 = 0.0f;
#pragma unroll
        for (int nt = 0; nt < 8; nt++) {
            sacc[nt][0] = __expf(sacc[nt][0] - mx0);
            sacc[nt][1] = __expf(sacc[nt][1] - mx0);
            sacc[nt][2] = __expf(sacc[nt][2] - mx1);
            sacc[nt][3] = __expf(sacc[nt][3] - mx1);
            sum0 += sacc[nt][0] + sacc[nt][1];
            sum1 += sacc[nt][2] + sacc[nt][3];
        }
        sum0 += __shfl_xor_sync(0xFFFFFFFFu, sum0, 1);
        sum0 += __shfl_xor_sync(0xFFFFFFFFu, sum0, 2);
        sum1 += __shfl_xor_sync(0xFFFFFFFFu, sum1, 1);
        sum1 += __shfl_xor_sync(0xFFFFFFFFu, sum1, 2);
        m0 = mx0; m1 = mx1;
        l0 = l0 * f0 + sum0;
        l1 = l1 * f1 + sum1;
#pragma unroll
        for (int d = 0; d < 16; d++) {
            o[d][0] *= f0; o[d][1] *= f0; o[d][2] *= f1; o[d][3] *= f1;
        }

        // ---- O += P V, 2-pass fp16, P hi/lo from registers ----
#pragma unroll
        for (int kt2 = 0; kt2 < 4; kt2++) {
            uint32_t Ph[4], Pl[4];
            Ph[0] = pack_hi_h(sacc[2 * kt2][0],     sacc[2 * kt2][1]);
            Pl[0] = pack_lo_h(sacc[2 * kt2][0],     sacc[2 * kt2][1],     Ph[0]);
            Ph[1] = pack_hi_h(sacc[2 * kt2][2],     sacc[2 * kt2][3]);
            Pl[1] = pack_lo_h(sacc[2 * kt2][2],     sacc[2 * kt2][3],     Ph[1]);
            Ph[2] = pack_hi_h(sacc[2 * kt2 + 1][0], sacc[2 * kt2 + 1][1]);
            Pl[2] = pack_lo_h(sacc[2 * kt2 + 1][0], sacc[2 * kt2 + 1][1], Ph[2]);
            Ph[3] = pack_hi_h(sacc[2 * kt2 + 1][2], sacc[2 * kt2 + 1][3]);
            Pl[3] = pack_lo_h(sacc[2 * kt2 + 1][2], sacc[2 * kt2 + 1][3], Ph[3]);

            const int kRow = kt2 * 16 + (lane & 7) + ((lane >> 4) & 1) * 8;
#pragma unroll
            for (int gd = 0; gd < 8; gd++) {
                const int nCol = gd * 16 + ((lane >> 3) & 1) * 8;
                const uint32_t off = (uint32_t)(kRow * ASTR + nCol) * 2;
                uint32_t vh[4];
                ldmatrix_x4t(vh[0], vh[1], vh[2], vh[3], sb + OFF_V + off);
                mma_f16(o[2 * gd],     Ph, vh[0], vh[2]);
                mma_f16(o[2 * gd],     Pl, vh[0], vh[2]);
                mma_f16(o[2 * gd + 1], Ph, vh[1], vh[3]);
                mma_f16(o[2 * gd + 1], Pl, vh[1], vh[3]);
            }
        }
    }

    // ---- epilogue: normalize, fp16 hi/lo store ----
    const float i0 = 1.0f / l0, i1 = 1.0f / l1;
    const int tok0 = b * S_ + q0 + wRow + (lane >> 2);
    const int tok1 = tok0 + 8;
    const int colB = h * HD_ + (lane & 3) * 2;
#pragma unroll
    for (int d = 0; d < 16; d++) {
        int col = colB + d * 8;
        float v0 = o[d][0] * i0, v1 = o[d][1] * i0;
        float v2 = o[d][2] * i1, v3 = o[d][3] * i1;
        uint32_t h01 = pack_hi_h(v0, v1);
        uint32_t h23 = pack_hi_h(v2, v3);
        *(uint32_t*)(outh + (size_t)tok0 * QSZ + col) = h01;
        *(uint32_t*)(outl + (size_t)tok0 * QSZ + col) = pack_lo_h(v0, v1, h01);
        *(uint32_t*)(outh + (size_t)tok1 * QSZ + col) = h23;
        *(uint32_t*)(outl + (size_t)tok1 * QSZ + col) = pack_lo_h(v2, v3, h23);
    }
}

// ============================================================================
// kernel_launch
// ============================================================================
extern "C" void kernel_launch(void* const* d_in, const int* in_sizes, int n_in,
                              void* d_out, int out_size) {
    const float* hs    = (const float*)d_in[0];
    const float* cosb  = (const float*)d_in[1];
    const float* sinb  = (const float*)d_in[2];
    const float* w_qkv = (const float*)d_in[3];
    const float* w_o   = (const float*)d_in[4];
    float* out = (float*)d_out;

    float* qkv;  cudaGetSymbolAddress((void**)&qkv, g_qkv);
    __half *hsh, *hsl, *wq, *wo, *ath, *atl;
    cudaGetSymbolAddress((void**)&hsh, g_hsh);
    cudaGetSymbolAddress((void**)&hsl, g_hsl);
    cudaGetSymbolAddress((void**)&wq,  g_wq);
    cudaGetSymbolAddress((void**)&wo,  g_wo);
    cudaGetSymbolAddress((void**)&ath, g_ath);
    cudaGetSymbolAddress((void**)&atl, g_atl);

    cudaFuncSetAttribute(gemm_h2, cudaFuncAttributeMaxDynamicSharedMemorySize, GEMM_SMEM);
    cudaFuncSetAttribute(attn_tc, cudaFuncAttributeMaxDynamicSharedMemorySize, ATTN_SMEM);

    // 0) operand conversion
    split2h_kernel<<<(TOK * HID_ / 4) / 256, 256>>>(hs, hsh, hsl, TOK * HID_ / 4);
    cvt_h_kernel<<<(OSZ * HID_ / 4) / 256, 256>>>(w_qkv, wq, OSZ * HID_ / 4);
    cvt_h_kernel<<<(HID_ * QSZ / 4) / 256, 256>>>(w_o, wo, HID_ * QSZ / 4);

    // 1) QKV projection
    gemm_h2<<<(TOK / 128) * (OSZ / 128), 512, GEMM_SMEM>>>(hsh, hsl, wq, qkv,
                                                           OSZ, HID_, OSZ / 128);
    // 2) RoPE
    rope_kernel<<<TOK * (NH_ + NKV_) * 64 / 256, 256>>>(qkv, cosb, sinb);

    // 3) Attention
    {
        dim3 grid(S_ / 128, B_ * NH_);
        attn_tc<<<grid, 256, ATTN_SMEM>>>(qkv, ath, atl);
    }

    // 4) Output projection
    gemm_h2<<<(TOK / 128) * (HID_ / 128), 512, GEMM_SMEM>>>(ath, atl, wo, out,
                                                            HID_, QSZ, HID_ / 128);
}

// round 9
// speedup vs baseline: 6.1013x; 1.6399x over previous
#include <cuda_runtime.h>
#include <cuda_bf16.h>
#include <cuda_fp16.h>
#include <cstdint>

// ===== Problem constants =====
#define B_    2
#define S_    2048
#define HID_  4096
#define NH_   32
#define NKV_  8
#define HD_   128
#define QSZ   (NH_ * HD_)
#define KVSZ  (NKV_ * HD_)
#define OSZ   (QSZ + 2 * KVSZ)     // 6144
#define TOK   (B_ * S_)            // 4096
#define SCALING 0.08838834764831843f

// ===== Scratch =====
__device__ float g_qkv[TOK * OSZ];
__device__ __half g_hs[TOK * HID_];
__device__ __half g_wq[OSZ * HID_];
__device__ __half g_wo[HID_ * QSZ];
__device__ __half g_at[TOK * QSZ];

// ============================================================================
// PTX helpers
// ============================================================================
__device__ __forceinline__ uint32_t smem_u32(const void* p) {
    uint32_t a;
    asm("{ .reg .u64 t; cvta.to.shared.u64 t, %1; cvt.u32.u64 %0, t; }" : "=r"(a) : "l"(p));
    return a;
}
__device__ __forceinline__ void ldmatrix_x4(uint32_t& r0, uint32_t& r1,
                                            uint32_t& r2, uint32_t& r3, uint32_t addr) {
    asm volatile("ldmatrix.sync.aligned.m8n8.x4.shared.b16 {%0,%1,%2,%3}, [%4];"
                 : "=r"(r0), "=r"(r1), "=r"(r2), "=r"(r3) : "r"(addr));
}
__device__ __forceinline__ void ldmatrix_x4t(uint32_t& r0, uint32_t& r1,
                                             uint32_t& r2, uint32_t& r3, uint32_t addr) {
    asm volatile("ldmatrix.sync.aligned.m8n8.x4.trans.shared.b16 {%0,%1,%2,%3}, [%4];"
                 : "=r"(r0), "=r"(r1), "=r"(r2), "=r"(r3) : "r"(addr));
}
__device__ __forceinline__ void mma_f16(float* d, const uint32_t* a, uint32_t b0, uint32_t b1) {
    asm volatile(
        "mma.sync.aligned.m16n8k16.row.col.f32.f16.f16.f32 "
        "{%0,%1,%2,%3}, {%4,%5,%6,%7}, {%8,%9}, {%0,%1,%2,%3};"
        : "+f"(d[0]), "+f"(d[1]), "+f"(d[2]), "+f"(d[3])
        : "r"(a[0]), "r"(a[1]), "r"(a[2]), "r"(a[3]), "r"(b0), "r"(b1));
}
__device__ __forceinline__ void cp_async16(uint32_t s, const void* g) {
    asm volatile("cp.async.cg.shared.global [%0], [%1], 16;" :: "r"(s), "l"(g) : "memory");
}
#define CP_COMMIT() asm volatile("cp.async.commit_group;" ::: "memory")
#define CP_WAIT1()  asm volatile("cp.async.wait_group 1;" ::: "memory")
#define CP_WAIT0()  asm volatile("cp.async.wait_group 0;" ::: "memory")

__device__ __forceinline__ uint32_t pack_hi_h(float a, float b) {
    __half2 h = __floats2half2_rn(a, b);
    return *(uint32_t*)&h;
}
__device__ __forceinline__ uint32_t pack_lo_h(float a, float b, uint32_t hi) {
    __half2 h = *(__half2*)&hi;
    __half2 l = __floats2half2_rn(a - __half2float(h.x), b - __half2float(h.y));
    return *(uint32_t*)&l;
}

// ============================================================================
// convert kernel: fp32 -> fp16
// ============================================================================
__global__ __launch_bounds__(256) void cvt_h_kernel(const float* __restrict__ in,
                                                    __half* __restrict__ o, int n4) {
    int i = blockIdx.x * blockDim.x + threadIdx.x;
    if (i >= n4) return;
    float4 v = ((const float4*)in)[i];
    ((uint2*)o)[i] = make_uint2(pack_hi_h(v.x, v.y), pack_hi_h(v.z, v.w));
}

// ============================================================================
// fp16 single-pass GEMM: C[M,N] = A[M,K] * B[N,K]^T
// 128x128x64 tile, 512 threads (16 warps, 4m x 4n), 3-stage cp.async pipeline,
// 2 CTAs/SM (smem 108KB, <=64 regs).
// ============================================================================
#define GBK    64
#define GSTR   72                    // fp16 elems per smem row (64 data + 8 pad)
#define GMATB  (128 * GSTR * 2)      // 18432 B
#define GSTAGEB (2 * GMATB)          // 36864 B (A, B)
#define GEMM_SMEM (3 * GSTAGEB)      // 110592 B

__global__ __launch_bounds__(512, 2) void gemm_h1(const __half* __restrict__ A,
                                                  const __half* __restrict__ Bw,
                                                  float* __restrict__ C,
                                                  int N, int K, int nBlkN) {
    extern __shared__ char sm[];
    const uint32_t sb = smem_u32(sm);

    int lin = blockIdx.x;
    int grp = lin / (8 * nBlkN);
    int rem = lin - grp * (8 * nBlkN);
    int bm  = grp * 8 + (rem & 7);
    int bn  = rem >> 3;

    const int t = threadIdx.x, lane = t & 31, wid = t >> 5;
    const int wm = wid & 3, wn = wid >> 2;

    const __half* mats[2] = { A + (size_t)bm * 128 * K, Bw + (size_t)bn * 128 * K };

    float acc[2][4][4];
#pragma unroll
    for (int i = 0; i < 2; i++)
#pragma unroll
        for (int j = 0; j < 4; j++)
#pragma unroll
            for (int k = 0; k < 4; k++) acc[i][j][k] = 0.0f;

    const int nchunk = K / GBK;

    auto issue = [&](int g) {
        const int s = g % 3;
        const uint32_t stg = sb + s * GSTAGEB;
        const int k0 = g * GBK;
#pragma unroll
        for (int m = 0; m < 2; m++) {
            const __half* src = mats[m] + k0;
            const uint32_t dstm = stg + m * GMATB;
#pragma unroll
            for (int i = 0; i < 2; i++) {
                int id  = t + i * 512;         // 0..1023
                int row = id >> 3, c = id & 7;
                cp_async16(dstm + (uint32_t)(row * GSTR + c * 8) * 2,
                           src + (size_t)row * K + c * 8);
            }
        }
        CP_COMMIT();
    };

    auto compute = [&](int st) {
        const uint32_t base = sb + st * GSTAGEB;
        const uint32_t aOff = (uint32_t)((wm * 32 + (lane & 15)) * GSTR + (lane >> 4) * 8) * 2;
        const uint32_t bOff = (uint32_t)((wn * 32 + (lane & 15)) * GSTR + (lane >> 4) * 8) * 2;
#pragma unroll
        for (int kk = 0; kk < 4; kk++) {
            const uint32_t ko = (uint32_t)(kk * 16) * 2;
            uint32_t af[2][4];
#pragma unroll
            for (int mt = 0; mt < 2; mt++) {
                uint32_t off = aOff + (uint32_t)(mt * 16 * GSTR) * 2 + ko;
                ldmatrix_x4(af[mt][0], af[mt][1], af[mt][2], af[mt][3], base + off);
            }
            uint32_t bf[2][4];
#pragma unroll
            for (int g = 0; g < 2; g++) {
                uint32_t off = bOff + (uint32_t)(g * 16 * GSTR) * 2 + ko;
                ldmatrix_x4(bf[g][0], bf[g][1], bf[g][2], bf[g][3], base + GMATB + off);
            }
#pragma unroll
            for (int mt = 0; mt < 2; mt++) {
#pragma unroll
                for (int g = 0; g < 2; g++) {
                    mma_f16(acc[mt][2 * g],     af[mt], bf[g][0], bf[g][2]);
                    mma_f16(acc[mt][2 * g + 1], af[mt], bf[g][1], bf[g][3]);
                }
            }
        }
    };

    issue(0); issue(1);
    for (int c = 0; c < nchunk; c++) {
        if (c < nchunk - 1) { CP_WAIT1(); } else { CP_WAIT0(); }
        __syncthreads();
        if (c + 2 < nchunk) issue(c + 2);   // writes stage (c-1)%3, consumed in iter c-1
        compute(c % 3);
    }

    const int rowBase = bm * 128 + wm * 32 + (lane >> 2);
    const int colBase = bn * 128 + wn * 32 + (lane & 3) * 2;
#pragma unroll
    for (int mt = 0; mt < 2; mt++) {
#pragma unroll
        for (int nt = 0; nt < 4; nt++) {
            float* c0 = C + (size_t)(rowBase + mt * 16) * N + colBase + nt * 8;
            *(float2*)c0                   = make_float2(acc[mt][nt][0], acc[mt][nt][1]);
            *(float2*)(c0 + (size_t)8 * N) = make_float2(acc[mt][nt][2], acc[mt][nt][3]);
        }
    }
}

// ============================================================================
// RoPE (fp32, in place on g_qkv)
// ============================================================================
__global__ __launch_bounds__(256) void rope_kernel(float* __restrict__ qkv,
                                                   const float* __restrict__ cosb,
                                                   const float* __restrict__ sinb) {
    int p = blockIdx.x * blockDim.x + threadIdx.x;
    int d    = p & 63;
    int rest = p >> 6;
    int hh   = rest % (NH_ + NKV_);
    int bs   = rest / (NH_ + NKV_);
    if (bs >= TOK) return;

    size_t base = (size_t)bs * OSZ;
    int off = (hh < NH_) ? (hh * HD_) : (QSZ + (hh - NH_) * HD_);

    float x1 = qkv[base + off + d];
    float x2 = qkv[base + off + d + 64];
    size_t cb = (size_t)bs * HD_;
    float c1 = cosb[cb + d],      s1 = sinb[cb + d];
    float c2 = cosb[cb + d + 64], s2 = sinb[cb + d + 64];

    qkv[base + off + d]      = x1 * c1 - x2 * s1;
    qkv[base + off + d + 64] = x2 * c2 + x1 * s2;
}

// ============================================================================
// Tensor-core flash attention, fp16 2-pass (validated in R8).
// Q = fp16 hi/lo, K = fp16 single; P = fp16 hi/lo, V = fp16 single.
// Output single fp16 (GEMM2's A operand).
// ============================================================================
#define ASTR 136
#define AQB  (128 * ASTR * 2)
#define AKB  (64 * ASTR * 2)
#define OFF_QH 0
#define OFF_QL (AQB)
#define OFF_K  (2 * AQB)
#define OFF_V  (2 * AQB + AKB)
#define ATTN_SMEM (2 * AQB + 2 * AKB)   // 104448 B

__global__ __launch_bounds__(256, 1) void attn_tc(const float* __restrict__ qkv,
                                                  __half* __restrict__ outh) {
    extern __shared__ char sm[];
    const uint32_t sb = smem_u32(sm);

    const int qt = (int)gridDim.x - 1 - (int)blockIdx.x;
    const int bh = blockIdx.y;
    const int b  = bh >> 5;
    const int h  = bh & 31;
    const int kvh = h >> 2;

    const float* qbase = qkv + (size_t)b * S_ * OSZ + h * HD_;
    const float* kbase = qkv + (size_t)b * S_ * OSZ + QSZ + kvh * HD_;
    const float* vbase = kbase + KVSZ;

    const int t = threadIdx.x, lane = t & 31, wid = t >> 5;
    const int q0 = qt * 128;
    const int wRow = wid * 16;

#pragma unroll
    for (int i = 0; i < 16; i++) {
        int idx = t + i * 256;
        int r   = idx >> 5;
        int c4  = (idx & 31) * 4;
        float4 v = *(const float4*)(qbase + (size_t)(q0 + r) * OSZ + c4);
        v.x *= SCALING; v.y *= SCALING; v.z *= SCALING; v.w *= SCALING;
        uint32_t h01 = pack_hi_h(v.x, v.y), h23 = pack_hi_h(v.z, v.w);
        uint32_t off = (uint32_t)(r * ASTR + c4) * 2;
        *(uint2*)(sm + OFF_QH + off) = make_uint2(h01, h23);
        *(uint2*)(sm + OFF_QL + off) = make_uint2(pack_lo_h(v.x, v.y, h01), pack_lo_h(v.z, v.w, h23));
    }

    float m0 = -1e30f, m1 = -1e30f, l0 = 0.0f, l1 = 0.0f;
    float o[16][4];
#pragma unroll
    for (int i = 0; i < 16; i++)
#pragma unroll
        for (int j = 0; j < 4; j++) o[i][j] = 0.0f;

    const int nkv = qt * 2 + 2;
    for (int kt = 0; kt < nkv; kt++) {
        const int k0 = kt * 64;

        float4 stg[16];
        {
            int r  = t >> 5;
            int c4 = (t & 31) * 4;
#pragma unroll
            for (int i = 0; i < 8; i++)
                stg[i] = *(const float4*)(kbase + (size_t)(k0 + r + i * 8) * OSZ + c4);
#pragma unroll
            for (int i = 0; i < 8; i++)
                stg[8 + i] = *(const float4*)(vbase + (size_t)(k0 + r + i * 8) * OSZ + c4);
        }
        __syncthreads();
        {
            int r  = t >> 5;
            int c4 = (t & 31) * 4;
#pragma unroll
            for (int i = 0; i < 8; i++) {
                uint32_t off = (uint32_t)((r + i * 8) * ASTR + c4) * 2;
                float4 v = stg[i];
                *(uint2*)(sm + OFF_K + off) = make_uint2(pack_hi_h(v.x, v.y), pack_hi_h(v.z, v.w));
                float4 w = stg[8 + i];
                *(uint2*)(sm + OFF_V + off) = make_uint2(pack_hi_h(w.x, w.y), pack_hi_h(w.z, w.w));
            }
        }
        __syncthreads();

        float sacc[8][4];
#pragma unroll
        for (int i = 0; i < 8; i++)
#pragma unroll
            for (int j = 0; j < 4; j++) sacc[i][j] = 0.0f;

        const uint32_t aOff = (uint32_t)((wRow + (lane & 15)) * ASTR + (lane >> 4) * 8) * 2;
        const uint32_t bOff = (uint32_t)(((lane & 15)) * ASTR + (lane >> 4) * 8) * 2;
#pragma unroll
        for (int kk = 0; kk < 8; kk++) {
            const uint32_t ko = (uint32_t)(kk * 16) * 2;
            uint32_t qh[4], ql[4];
            ldmatrix_x4(qh[0], qh[1], qh[2], qh[3], sb + OFF_QH + aOff + ko);
            ldmatrix_x4(ql[0], ql[1], ql[2], ql[3], sb + OFF_QL + aOff + ko);
#pragma unroll
            for (int g = 0; g < 4; g++) {
                uint32_t off = bOff + (uint32_t)(g * 16 * ASTR) * 2 + ko;
                uint32_t kh[4];
                ldmatrix_x4(kh[0], kh[1], kh[2], kh[3], sb + OFF_K + off);
                mma_f16(sacc[2 * g],     qh, kh[0], kh[2]);
                mma_f16(sacc[2 * g],     ql, kh[0], kh[2]);
                mma_f16(sacc[2 * g + 1], qh, kh[1], kh[3]);
                mma_f16(sacc[2 * g + 1], ql, kh[1], kh[3]);
            }
        }

        const int r0 = q0 + wRow + (lane >> 2);
        const int r1 = r0 + 8;
        if (k0 + 63 > q0 + wRow) {
#pragma unroll
            for (int nt = 0; nt < 8; nt++) {
                int c = k0 + nt * 8 + (lane & 3) * 2;
                if (c     > r0) sacc[nt][0] = -1e30f;
                if (c + 1 > r0) sacc[nt][1] = -1e30f;
                if (c     > r1) sacc[nt][2] = -1e30f;
                if (c + 1 > r1) sacc[nt][3] = -1e30f;
            }
        }

        float mx0 = m0, mx1 = m1;
#pragma unroll
        for (int nt = 0; nt < 8; nt++) {
            mx0 = fmaxf(mx0, fmaxf(sacc[nt][0], sacc[nt][1]));
            mx1 = fmaxf(mx1, fmaxf(sacc[nt][2], sacc[nt][3]));
        }
        mx0 = fmaxf(mx0, __shfl_xor_sync(0xFFFFFFFFu, mx0, 1));
        mx0 = fmaxf(mx0, __shfl_xor_sync(0xFFFFFFFFu, mx0, 2));
        mx1 = fmaxf(mx1, __shfl_xor_sync(0xFFFFFFFFu, mx1, 1));
        mx1 = fmaxf(mx1, __shfl_xor_sync(0xFFFFFFFFu, mx1, 2));
        float f0 = __expf(m0 - mx0), f1 = __expf(m1 - mx1);
        float sum0 = 0.0f, sum1 = 0.0f;
#pragma unroll
        for (int nt = 0; nt < 8; nt++) {
            sacc[nt][0] = __expf(sacc[nt][0] - mx0);
            sacc[nt][1] = __expf(sacc[nt][1] - mx0);
            sacc[nt][2] = __expf(sacc[nt][2] - mx1);
            sacc[nt][3] = __expf(sacc[nt][3] - mx1);
            sum0 += sacc[nt][0] + sacc[nt][1];
            sum1 += sacc[nt][2] + sacc[nt][3];
        }
        sum0 += __shfl_xor_sync(0xFFFFFFFFu, sum0, 1);
        sum0 += __shfl_xor_sync(0xFFFFFFFFu, sum0, 2);
        sum1 += __shfl_xor_sync(0xFFFFFFFFu, sum1, 1);
        sum1 += __shfl_xor_sync(0xFFFFFFFFu, sum1, 2);
        m0 = mx0; m1 = mx1;
        l0 = l0 * f0 + sum0;
        l1 = l1 * f1 + sum1;
#pragma unroll
        for (int d = 0; d < 16; d++) {
            o[d][0] *= f0; o[d][1] *= f0; o[d][2] *= f1; o[d][3] *= f1;
        }

#pragma unroll
        for (int kt2 = 0; kt2 < 4; kt2++) {
            uint32_t Ph[4], Pl[4];
            Ph[0] = pack_hi_h(sacc[2 * kt2][0],     sacc[2 * kt2][1]);
            Pl[0] = pack_lo_h(sacc[2 * kt2][0],     sacc[2 * kt2][1],     Ph[0]);
            Ph[1] = pack_hi_h(sacc[2 * kt2][2],     sacc[2 * kt2][3]);
            Pl[1] = pack_lo_h(sacc[2 * kt2][2],     sacc[2 * kt2][3],     Ph[1]);
            Ph[2] = pack_hi_h(sacc[2 * kt2 + 1][0], sacc[2 * kt2 + 1][1]);
            Pl[2] = pack_lo_h(sacc[2 * kt2 + 1][0], sacc[2 * kt2 + 1][1], Ph[2]);
            Ph[3] = pack_hi_h(sacc[2 * kt2 + 1][2], sacc[2 * kt2 + 1][3]);
            Pl[3] = pack_lo_h(sacc[2 * kt2 + 1][2], sacc[2 * kt2 + 1][3], Ph[3]);

            const int kRow = kt2 * 16 + (lane & 7) + ((lane >> 4) & 1) * 8;
#pragma unroll
            for (int gd = 0; gd < 8; gd++) {
                const int nCol = gd * 16 + ((lane >> 3) & 1) * 8;
                const uint32_t off = (uint32_t)(kRow * ASTR + nCol) * 2;
                uint32_t vh[4];
                ldmatrix_x4t(vh[0], vh[1], vh[2], vh[3], sb + OFF_V + off);
                mma_f16(o[2 * gd],     Ph, vh[0], vh[2]);
                mma_f16(o[2 * gd],     Pl, vh[0], vh[2]);
                mma_f16(o[2 * gd + 1], Ph, vh[1], vh[3]);
                mma_f16(o[2 * gd + 1], Pl, vh[1], vh[3]);
            }
        }
    }

    const float i0 = 1.0f / l0, i1 = 1.0f / l1;
    const int tok0 = b * S_ + q0 + wRow + (lane >> 2);
    const int tok1 = tok0 + 8;
    const int colB = h * HD_ + (lane & 3) * 2;
#pragma unroll
    for (int d = 0; d < 16; d++) {
        int col = colB + d * 8;
        *(uint32_t*)(outh + (size_t)tok0 * QSZ + col) = pack_hi_h(o[d][0] * i0, o[d][1] * i0);
        *(uint32_t*)(outh + (size_t)tok1 * QSZ + col) = pack_hi_h(o[d][2] * i1, o[d][3] * i1);
    }
}

// ============================================================================
// kernel_launch
// ============================================================================
extern "C" void kernel_launch(void* const* d_in, const int* in_sizes, int n_in,
                              void* d_out, int out_size) {
    const float* hs    = (const float*)d_in[0];
    const float* cosb  = (const float*)d_in[1];
    const float* sinb  = (const float*)d_in[2];
    const float* w_qkv = (const float*)d_in[3];
    const float* w_o   = (const float*)d_in[4];
    float* out = (float*)d_out;

    float* qkv;  cudaGetSymbolAddress((void**)&qkv, g_qkv);
    __half *hsp, *wq, *wo, *at;
    cudaGetSymbolAddress((void**)&hsp, g_hs);
    cudaGetSymbolAddress((void**)&wq,  g_wq);
    cudaGetSymbolAddress((void**)&wo,  g_wo);
    cudaGetSymbolAddress((void**)&at,  g_at);

    cudaFuncSetAttribute(gemm_h1, cudaFuncAttributeMaxDynamicSharedMemorySize, GEMM_SMEM);
    cudaFuncSetAttribute(attn_tc, cudaFuncAttributeMaxDynamicSharedMemorySize, ATTN_SMEM);

    // 0) operand conversion
    cvt_h_kernel<<<(TOK * HID_ / 4) / 256, 256>>>(hs, hsp, TOK * HID_ / 4);
    cvt_h_kernel<<<(OSZ * HID_ / 4) / 256, 256>>>(w_qkv, wq, OSZ * HID_ / 4);
    cvt_h_kernel<<<(HID_ * QSZ / 4) / 256, 256>>>(w_o, wo, HID_ * QSZ / 4);

    // 1) QKV projection
    gemm_h1<<<(TOK / 128) * (OSZ / 128), 512, GEMM_SMEM>>>(hsp, wq, qkv,
                                                           OSZ, HID_, OSZ / 128);
    // 2) RoPE
    rope_kernel<<<TOK * (NH_ + NKV_) * 64 / 256, 256>>>(qkv, cosb, sinb);

    // 3) Attention
    {
        dim3 grid(S_ / 128, B_ * NH_);
        attn_tc<<<grid, 256, ATTN_SMEM>>>(qkv, at);
    }

    // 4) Output projection
    gemm_h1<<<(TOK / 128) * (HID_ / 128), 512, GEMM_SMEM>>>(at, wo, out,
                                                            HID_, QSZ, HID_ / 128);
}